// round 11
// baseline (speedup 1.0000x reference)
#include <cuda_runtime.h>

#define NN 3000
#define TT 20
#define IND 6
#define HD 64
#define NH 8
#define MAXNZ 512
#define NGRU (NN / 4)          // 750 gru blocks
#define NCOMP (2 * NN)         // 6000 compact blocks

// ---------------- scratch (no allocation allowed) ----------------
__device__ ulonglong2 g_Whh4[(HD / 2) * 192];  // [kpair][row] -> (pk(w_k), pk(w_k+1))
__device__ float g_support[NN * HD];        // GRU final hidden
__device__ float g_s[2][NN * HD];           // per-graph head features  [n][h*8+f]
__device__ float g_f1[2][NH * NN];          // source scores  [g][h*N+n]
__device__ float g_f2[2][NH * NN];          // dest scores    [g][h*N+n]
__device__ unsigned g_f1maxI[16];           // encoded global per-(g,h) max of f1
__device__ int   g_nnz[2 * NN];             // CSR row counts
__device__ short g_cidx[(size_t)2 * NN * MAXNZ];  // CSR column lists
__device__ float g_att[2][NN * HD];         // attention outputs
__device__ float g_emb[NN * HD];            // pre-pairnorm embedding
__device__ float g_colsum[HD];              // column sums for pairnorm mean

__device__ __forceinline__ float sigm(float x) { return 1.0f / (1.0f + __expf(-x)); }
__device__ __forceinline__ float tanhfast(float x) { return 2.0f * sigm(2.0f * x) - 1.0f; }

// order-preserving float<->uint encoding for atomicMax
__device__ __forceinline__ unsigned fenc(float f) {
    unsigned u = __float_as_uint(f);
    return (u & 0x80000000u) ? ~u : (u | 0x80000000u);
}
__device__ __forceinline__ float fdec(unsigned u) {
    return __uint_as_float((u & 0x80000000u) ? (u & 0x7fffffffu) : ~u);
}

// packed f32x2 helpers
__device__ __forceinline__ unsigned long long pk(float lo, float hi) {
    unsigned long long r;
    asm("mov.b64 %0, {%1,%2};" : "=l"(r) : "f"(lo), "f"(hi));
    return r;
}
__device__ __forceinline__ void upk(unsigned long long v, float& lo, float& hi) {
    asm("mov.b64 {%0,%1}, %2;" : "=f"(lo), "=f"(hi) : "l"(v));
}
__device__ __forceinline__ void ffma2(unsigned long long& d, unsigned long long a, unsigned long long b) {
    asm("fma.rn.f32x2 %0, %1, %2, %0;" : "+l"(d) : "l"(a), "l"(b));
}

// ---------------- K0: pack Whh into k-pair LDG.128 layout + init reductions ----------------
__global__ void prep_kernel(const float* __restrict__ Whh) {
    int i = blockIdx.x * 256 + threadIdx.x;
    if (i < 192 * HD) {
        int r = i >> 6, k = i & 63;
        float w = Whh[i];
        unsigned long long pw = pk(w, w);
        if (k & 1) g_Whh4[(k >> 1) * 192 + r].y = pw;
        else       g_Whh4[(k >> 1) * 192 + r].x = pw;
    }
    if (blockIdx.x == 0 && threadIdx.x < HD) g_colsum[threadIdx.x] = 0.f;
    if (blockIdx.x == 0 && threadIdx.x < 16) g_f1maxI[threadIdx.x] = 0u;
}

// ---------------- K1: fused [GRU blocks | adjacency-compaction blocks] ----------------
__global__ void __launch_bounds__(64) fused_kernel(
        const float* __restrict__ x, const float* __restrict__ Wih,
        const float* __restrict__ bih, const float* __restrict__ bhh,
        const float* __restrict__ Wp, const float* __restrict__ Wn,
        const float* __restrict__ Wup, const float* __restrict__ Wvp,
        const float* __restrict__ Wun, const float* __restrict__ Wvn,
        const float* __restrict__ adj0, const float* __restrict__ adj1) {
    if (blockIdx.x < NGRU) {
        // ================= GRU body (4 nodes / 64-thread block) =================
        __shared__ float4 shh4[2][HD];      // ping-pong hidden
        __shared__ float shx[TT * IND * 4]; // preloaded inputs
        int j = threadIdx.x;
        int node0 = blockIdx.x * 4;

        // preload all inputs for 4 nodes x 20 steps (coalesced)
#pragma unroll
        for (int e = j; e < TT * IND * 4; e += 64) {
            int b = e / (TT * IND), rem = e % (TT * IND);
            shx[rem * 4 + b] = x[node0 * (TT * IND) + e];
        }

        unsigned long long pwr[IND], pwz[IND], pwn[IND];
#pragma unroll
        for (int c = 0; c < IND; c++) {
            float a = Wih[j * IND + c];
            float b = Wih[(64 + j) * IND + c];
            float d = Wih[(128 + j) * IND + c];
            pwr[c] = pk(a, a); pwz[c] = pk(b, b); pwn[c] = pk(d, d);
        }
        float br  = bih[j] + bhh[j];
        float bz  = bih[64 + j] + bhh[64 + j];
        float bin = bih[128 + j];
        float bhn = bhh[128 + j];
        unsigned long long pbr = pk(br, br), pbz = pk(bz, bz);
        unsigned long long pbi = pk(bin, bin), pbh = pk(bhn, bhn);

        shh4[0][j] = make_float4(0.f, 0.f, 0.f, 0.f);
        float h0 = 0.f, h1 = 0.f, h2 = 0.f, h3 = 0.f;
        int cur = 0;
        __syncthreads();   // shx + zeroed shh visible

        for (int t = 0; t < TT; t++) {
            const float4* xt = (const float4*)(shx + t * IND * 4);

            unsigned long long ar01 = pbr, ar23 = pbr;
            unsigned long long az01 = pbz, az23 = pbz;
            unsigned long long an01 = pbi, an23 = pbi;
            unsigned long long gn01 = pbh, gn23 = pbh;

#pragma unroll
            for (int c = 0; c < IND; c++) {
                float4 xv = xt[c];
                unsigned long long x01 = pk(xv.x, xv.y), x23 = pk(xv.z, xv.w);
                ffma2(ar01, pwr[c], x01); ffma2(ar23, pwr[c], x23);
                ffma2(az01, pwz[c], x01); ffma2(az23, pwz[c], x23);
                ffma2(an01, pwn[c], x01); ffma2(an23, pwn[c], x23);
            }

            const float4* hbuf = shh4[cur];
#pragma unroll 4
            for (int p = 0; p < HD / 2; p++) {
                float4 hva = hbuf[2 * p], hvb = hbuf[2 * p + 1];
                unsigned long long ha01 = pk(hva.x, hva.y), ha23 = pk(hva.z, hva.w);
                unsigned long long hb01 = pk(hvb.x, hvb.y), hb23 = pk(hvb.z, hvb.w);
                ulonglong2 wr = g_Whh4[p * 192 + j];
                ulonglong2 wz = g_Whh4[p * 192 + 64 + j];
                ulonglong2 wn_ = g_Whh4[p * 192 + 128 + j];
                ffma2(ar01, wr.x, ha01);  ffma2(ar23, wr.x, ha23);
                ffma2(az01, wz.x, ha01);  ffma2(az23, wz.x, ha23);
                ffma2(gn01, wn_.x, ha01); ffma2(gn23, wn_.x, ha23);
                ffma2(ar01, wr.y, hb01);  ffma2(ar23, wr.y, hb23);
                ffma2(az01, wz.y, hb01);  ffma2(az23, wz.y, hb23);
                ffma2(gn01, wn_.y, hb01); ffma2(gn23, wn_.y, hb23);
            }

            float a0, a1, a2, a3, z0, z1, z2, z3, n0, n1, n2, n3, g0, g1, g2, g3;
            upk(ar01, a0, a1); upk(ar23, a2, a3);
            upk(az01, z0, z1); upk(az23, z2, z3);
            upk(an01, n0, n1); upk(an23, n2, n3);
            upk(gn01, g0, g1); upk(gn23, g2, g3);

            float r0 = sigm(a0), r1 = sigm(a1), r2 = sigm(a2), r3 = sigm(a3);
            float zz0 = sigm(z0), zz1 = sigm(z1), zz2 = sigm(z2), zz3 = sigm(z3);
            float nv0 = tanhfast(n0 + r0 * g0);
            float nv1 = tanhfast(n1 + r1 * g1);
            float nv2 = tanhfast(n2 + r2 * g2);
            float nv3 = tanhfast(n3 + r3 * g3);
            h0 = (1.f - zz0) * nv0 + zz0 * h0;
            h1 = (1.f - zz1) * nv1 + zz1 * h1;
            h2 = (1.f - zz2) * nv2 + zz2 * h2;
            h3 = (1.f - zz3) * nv3 + zz3 * h3;
            shh4[cur ^ 1][j] = make_float4(h0, h1, h2, h3);
            __syncthreads();   // single barrier per step (ping-pong)
            cur ^= 1;
        }

        g_support[(node0 + 0) * HD + j] = h0;
        g_support[(node0 + 1) * HD + j] = h1;
        g_support[(node0 + 2) * HD + j] = h2;
        g_support[(node0 + 3) * HD + j] = h3;

        // fused head projection: s = h @ W, f1/f2, global f1 max
        int hh = j >> 3, f = j & 7;
        const float* hsm = (const float*)shh4[cur];
#pragma unroll
        for (int g = 0; g < 2; g++) {
            const float* W  = g ? Wn  : Wp;
            float wu = (g ? Wun : Wup)[hh * 8 + f];
            float wv = (g ? Wvn : Wvp)[hh * 8 + f];
            float acc[4] = {0.f, 0.f, 0.f, 0.f};
#pragma unroll 4
            for (int k = 0; k < HD; k++) {
                float w = W[k * HD + j];
#pragma unroll
                for (int b = 0; b < 4; b++) acc[b] += hsm[k * 4 + b] * w;
            }
#pragma unroll
            for (int b = 0; b < 4; b++) {
                int n = node0 + b;
                g_s[g][n * HD + j] = acc[b];
                float t1 = acc[b] * wu, t2 = acc[b] * wv;
#pragma unroll
                for (int o = 4; o; o >>= 1) {
                    t1 += __shfl_xor_sync(0xffffffffu, t1, o);
                    t2 += __shfl_xor_sync(0xffffffffu, t2, o);
                }
                if (f == 0) {
                    g_f1[g][hh * NN + n] = t1;
                    g_f2[g][hh * NN + n] = t2;
                    atomicMax(&g_f1maxI[g * 8 + hh], fenc(t1));
                }
            }
        }
    } else {
        // ================= adjacency compaction body (1 row / 64-thread block) =================
        int r = blockIdx.x - NGRU;          // 0..5999
        int g = (r >= NN) ? 1 : 0;
        int i = r - g * NN;
        const float* row = (g ? adj1 : adj0) + (size_t)i * NN;
        __shared__ short sidx[MAXNZ];
        __shared__ int scnt;
        int tid = threadIdx.x, lane = tid & 31;
        if (tid == 0) scnt = 0;
        __syncthreads();

        const float4* row4 = (const float4*)row;
#pragma unroll 2
        for (int it = 0; it < 12; it++) {
            int q = it * 64 + tid;
            float4 v = (q < NN / 4) ? row4[q] : make_float4(0.f, 0.f, 0.f, 0.f);
#pragma unroll
            for (int c = 0; c < 4; c++) {
                float val = (c == 0) ? v.x : (c == 1) ? v.y : (c == 2) ? v.z : v.w;
                unsigned bal = __ballot_sync(0xffffffffu, val != 0.f);
                if (bal) {
                    int leader = __ffs(bal) - 1;
                    int base;
                    if (lane == leader) base = atomicAdd(&scnt, __popc(bal));
                    base = __shfl_sync(0xffffffffu, base, leader);
                    if (val != 0.f) {
                        int p = base + __popc(bal & ((1u << lane) - 1u));
                        if (p < MAXNZ) sidx[p] = (short)(4 * q + c);
                    }
                }
            }
        }
        __syncthreads();
        int m = min(scnt, MAXNZ);
        size_t base = (size_t)(g * NN + i) * MAXNZ;
        for (int k = tid; k < m; k += 64) g_cidx[base + k] = sidx[k];
        if (tid == 0) g_nnz[g * NN + i] = m;
    }
}

// ---------------- K3: attention gather from CSR (grid: [N, 2], 256 thr, no barriers) ----------------
__global__ void attn_kernel() {
    int i = blockIdx.x, g = blockIdx.y;
    int tid = threadIdx.x, lane = tid & 31;
    int m = g_nnz[g * NN + i];
    const short* list = g_cidx + (size_t)(g * NN + i) * MAXNZ;

    int h = tid >> 5;                         // warp = head
    const float* f1h = g_f1[g] + h * NN;
    float f2v = g_f2[g][h * NN + i];
    // shift M >= max over row nonzeros (leaky monotone; softmax shift-invariant)
    float Mv = fdec(g_f1maxI[g * 8 + h]) + f2v;
    Mv = Mv >= 0.f ? Mv : 0.2f * Mv;
    const float* sb = g_s[g];

    float se = 0.f;
    float acc[8] = {0, 0, 0, 0, 0, 0, 0, 0};
    for (int k = lane; k < m; k += 32) {
        int jj = list[k];
        float vv = f1h[jj] + f2v;
        vv = vv >= 0.f ? vv : 0.2f * vv;
        float e = __expf(vv - Mv);
        se += e;
        const float4* sp = (const float4*)(sb + jj * HD + h * 8);
        float4 a = sp[0], bb = sp[1];
        acc[0] += e * a.x;  acc[1] += e * a.y;  acc[2] += e * a.z;  acc[3] += e * a.w;
        acc[4] += e * bb.x; acc[5] += e * bb.y; acc[6] += e * bb.z; acc[7] += e * bb.w;
    }
#pragma unroll
    for (int o = 16; o; o >>= 1) {
        se += __shfl_xor_sync(0xffffffffu, se, o);
#pragma unroll
        for (int f = 0; f < 8; f++) acc[f] += __shfl_xor_sync(0xffffffffu, acc[f], o);
    }
    if (lane == 0) {
        float inv = se > 0.f ? 1.0f / se : 0.f;   // empty row -> zeros (matches ref mask)
        float* o2 = g_att[g] + i * HD + h * 8;
#pragma unroll
        for (int f = 0; f < 8; f++) o2[f] = acc[f] * inv;
    }
}

// ---------------- K4: warp-per-2-nodes, float2 channel pairing (grid: N/8, block 128) ----------------
__global__ void __launch_bounds__(128) comb_kernel(
        const float* __restrict__ pos_b, const float* __restrict__ pWp, const float* __restrict__ pbp,
        const float* __restrict__ neg_b, const float* __restrict__ pWn, const float* __restrict__ pbn,
        const float* __restrict__ selfW, const float* __restrict__ selfb,
        const float* __restrict__ mpW, const float* __restrict__ mpb,
        const float* __restrict__ mnW, const float* __restrict__ mnb,
        const float* __restrict__ semW1, const float* __restrict__ semb1,
        const float* __restrict__ semW2) {
    __shared__ float sb[4][12][HD];     // per-warp staging
    __shared__ float colacc[HD];
    int tid = threadIdx.x, warp = tid >> 5, lane = tid & 31;
    int nA = blockIdx.x * 8 + warp * 2;   // 375*8 = 3000 exact
    int nB = nA + 1;
    int c0 = 2 * lane, c1 = 2 * lane + 1;

    if (tid < HD) colacc[tid] = 0.f;
    __syncthreads();

    const float2* pWp2 = (const float2*)pWp;
    const float2* pWn2 = (const float2*)pWn;
    const float2* sfW2 = (const float2*)selfW;
    const float2* mpW2 = (const float2*)mpW;
    const float2* mnW2 = (const float2*)mnW;
    const float2* sm12 = (const float2*)semW1;

    float (*S)[HD] = sb[warp];
    {
        float2 sA = ((const float2*)(g_support + nA * HD))[lane];
        float2 sB = ((const float2*)(g_support + nB * HD))[lane];
        S[0][c0] = sA.x; S[0][c1] = sA.y;
        S[1][c0] = sB.x; S[1][c1] = sB.y;
    }
    __syncwarp();

    // ---- phase 1 ----
    float2 pb2  = ((const float2*)pos_b)[lane];
    float2 pbp2 = ((const float2*)pbp)[lane];
    float2 nb2  = ((const float2*)neg_b)[lane];
    float2 pbn2 = ((const float2*)pbn)[lane];
    float2 sfb2 = ((const float2*)selfb)[lane];
    float2 atpA = ((const float2*)(g_att[0] + nA * HD))[lane];
    float2 atpB = ((const float2*)(g_att[0] + nB * HD))[lane];
    float2 atnA = ((const float2*)(g_att[1] + nA * HD))[lane];
    float2 atnB = ((const float2*)(g_att[1] + nB * HD))[lane];
    float apA0 = atpA.x + pb2.x + pbp2.x, apA1 = atpA.y + pb2.y + pbp2.y;
    float apB0 = atpB.x + pb2.x + pbp2.x, apB1 = atpB.y + pb2.y + pbp2.y;
    float anA0 = atnA.x + nb2.x + pbn2.x, anA1 = atnA.y + nb2.y + pbn2.y;
    float anB0 = atnB.x + nb2.x + pbn2.x, anB1 = atnB.y + nb2.y + pbn2.y;
    float svA0 = sfb2.x, svA1 = sfb2.y, svB0 = sfb2.x, svB1 = sfb2.y;
#pragma unroll 8
    for (int k = 0; k < HD; k++) {
        float sA = S[0][k], sBv = S[1][k];
        float2 wp = pWp2[k * 32 + lane];
        float2 wn = pWn2[k * 32 + lane];
        float2 ws = sfW2[k * 32 + lane];
        apA0 += sA * wp.x;  apA1 += sA * wp.y;  apB0 += sBv * wp.x;  apB1 += sBv * wp.y;
        anA0 += sA * wn.x;  anA1 += sA * wn.y;  anB0 += sBv * wn.x;  anB1 += sBv * wn.y;
        svA0 += sA * ws.x;  svA1 += sA * ws.y;  svB0 += sBv * ws.x;  svB1 += sBv * ws.y;
    }
    S[2][c0] = apA0; S[2][c1] = apA1; S[3][c0] = apB0; S[3][c1] = apB1;
    S[4][c0] = anA0; S[4][c1] = anA1; S[5][c0] = anB0; S[5][c1] = anB1;
    __syncwarp();

    // ---- phase 2 ----
    float2 mpb2 = ((const float2*)mpb)[lane];
    float2 mnb2 = ((const float2*)mnb)[lane];
    float spA0 = mpb2.x, spA1 = mpb2.y, spB0 = mpb2.x, spB1 = mpb2.y;
    float snA0 = mnb2.x, snA1 = mnb2.y, snB0 = mnb2.x, snB1 = mnb2.y;
#pragma unroll 8
    for (int k = 0; k < HD; k++) {
        float pA = S[2][k], pB = S[3][k], qA = S[4][k], qB = S[5][k];
        float2 w = mpW2[k * 32 + lane];
        float2 v = mnW2[k * 32 + lane];
        spA0 += pA * w.x; spA1 += pA * w.y; spB0 += pB * w.x; spB1 += pB * w.y;
        snA0 += qA * v.x; snA1 += qA * v.y; snB0 += qB * v.x; snB1 += qB * v.y;
    }
    S[6][c0] = svA0; S[6][c1] = svA1; S[7][c0] = svB0; S[7][c1] = svB1;
    S[8][c0] = spA0; S[8][c1] = spA1; S[9][c0] = spB0; S[9][c1] = spB1;
    S[10][c0] = snA0; S[10][c1] = snA1; S[11][c0] = snB0; S[11][c1] = snB1;
    __syncwarp();

    // ---- phase 3: semantic attention logits ----
    float2 sb12 = ((const float2*)semb1)[lane];
    float tA00 = sb12.x, tA01 = sb12.y, tA10 = sb12.x, tA11 = sb12.y, tA20 = sb12.x, tA21 = sb12.y;
    float tB00 = sb12.x, tB01 = sb12.y, tB10 = sb12.x, tB11 = sb12.y, tB20 = sb12.x, tB21 = sb12.y;
#pragma unroll 8
    for (int k = 0; k < HD; k++) {
        float2 w = sm12[k * 32 + lane];
        float e0A = S[6][k], e0B = S[7][k];
        float e1A = S[8][k], e1B = S[9][k];
        float e2A = S[10][k], e2B = S[11][k];
        tA00 += e0A * w.x; tA01 += e0A * w.y; tB00 += e0B * w.x; tB01 += e0B * w.y;
        tA10 += e1A * w.x; tA11 += e1A * w.y; tB10 += e1B * w.x; tB11 += e1B * w.y;
        tA20 += e2A * w.x; tA21 += e2A * w.y; tB20 += e2B * w.x; tB21 += e2B * w.y;
    }
    float2 w22 = ((const float2*)semW2)[lane];
    float uA0 = tanhfast(tA00) * w22.x + tanhfast(tA01) * w22.y;
    float uA1 = tanhfast(tA10) * w22.x + tanhfast(tA11) * w22.y;
    float uA2 = tanhfast(tA20) * w22.x + tanhfast(tA21) * w22.y;
    float uB0 = tanhfast(tB00) * w22.x + tanhfast(tB01) * w22.y;
    float uB1 = tanhfast(tB10) * w22.x + tanhfast(tB11) * w22.y;
    float uB2 = tanhfast(tB20) * w22.x + tanhfast(tB21) * w22.y;
#pragma unroll
    for (int o = 16; o; o >>= 1) {
        uA0 += __shfl_xor_sync(0xffffffffu, uA0, o);
        uA1 += __shfl_xor_sync(0xffffffffu, uA1, o);
        uA2 += __shfl_xor_sync(0xffffffffu, uA2, o);
        uB0 += __shfl_xor_sync(0xffffffffu, uB0, o);
        uB1 += __shfl_xor_sync(0xffffffffu, uB1, o);
        uB2 += __shfl_xor_sync(0xffffffffu, uB2, o);
    }
    float mA = fmaxf(uA0, fmaxf(uA1, uA2));
    float eA0 = __expf(uA0 - mA), eA1 = __expf(uA1 - mA), eA2 = __expf(uA2 - mA);
    float invA = 1.f / (eA0 + eA1 + eA2);
    float embA0 = (eA0 * svA0 + eA1 * spA0 + eA2 * snA0) * invA;
    float embA1 = (eA0 * svA1 + eA1 * spA1 + eA2 * snA1) * invA;
    float mB = fmaxf(uB0, fmaxf(uB1, uB2));
    float eB0 = __expf(uB0 - mB), eB1 = __expf(uB1 - mB), eB2 = __expf(uB2 - mB);
    float invB = 1.f / (eB0 + eB1 + eB2);
    float embB0 = (eB0 * svB0 + eB1 * spB0 + eB2 * snB0) * invB;
    float embB1 = (eB0 * svB1 + eB1 * spB1 + eB2 * snB1) * invB;

    ((float2*)(g_emb + nA * HD))[lane] = make_float2(embA0, embA1);
    ((float2*)(g_emb + nB * HD))[lane] = make_float2(embB0, embB1);
    atomicAdd(&colacc[c0], embA0 + embB0);
    atomicAdd(&colacc[c1], embA1 + embB1);
    __syncthreads();
    if (tid < HD) atomicAdd(&g_colsum[tid], colacc[tid]);
}

// ---------------- K5: pairnorm + prediction head (warp per node) ----------------
__global__ void final_kernel(const float* __restrict__ predW, const float* __restrict__ predb,
                             float* __restrict__ out) {
    int warp = threadIdx.x >> 5, lane = threadIdx.x & 31;
    int n = blockIdx.x * 4 + warp;
    float invn = 1.0f / NN;
    float x0 = g_emb[n * HD + lane]      - g_colsum[lane]      * invn;
    float x1 = g_emb[n * HD + 32 + lane] - g_colsum[32 + lane] * invn;
    float ss = x0 * x0 + x1 * x1;
    float dt = x0 * predW[lane] + x1 * predW[32 + lane];
#pragma unroll
    for (int o = 16; o; o >>= 1) {
        ss += __shfl_xor_sync(0xffffffffu, ss, o);
        dt += __shfl_xor_sync(0xffffffffu, dt, o);
    }
    if (lane == 0) out[n] = sigm(dt * rsqrtf(1e-6f + ss) + predb[0]);
}

// ---------------- launch ----------------
extern "C" void kernel_launch(void* const* d_in, const int* in_sizes, int n_in,
                              void* d_out, int out_size) {
    (void)in_sizes; (void)n_in; (void)out_size;
    const float* inputs   = (const float*)d_in[0];
    const float* pos_adj  = (const float*)d_in[1];
    const float* neg_adj  = (const float*)d_in[2];
    const float* Wih      = (const float*)d_in[3];
    const float* Whh      = (const float*)d_in[4];
    const float* bih      = (const float*)d_in[5];
    const float* bhh      = (const float*)d_in[6];
    const float* pos_W    = (const float*)d_in[7];
    const float* pos_Wu   = (const float*)d_in[8];
    const float* pos_Wv   = (const float*)d_in[9];
    const float* pos_b    = (const float*)d_in[10];
    const float* pos_projW= (const float*)d_in[11];
    const float* pos_projb= (const float*)d_in[12];
    const float* neg_W    = (const float*)d_in[13];
    const float* neg_Wu   = (const float*)d_in[14];
    const float* neg_Wv   = (const float*)d_in[15];
    const float* neg_b    = (const float*)d_in[16];
    const float* neg_projW= (const float*)d_in[17];
    const float* neg_projb= (const float*)d_in[18];
    const float* self_W   = (const float*)d_in[19];
    const float* self_b   = (const float*)d_in[20];
    const float* mlpp_W   = (const float*)d_in[21];
    const float* mlpp_b   = (const float*)d_in[22];
    const float* mlpn_W   = (const float*)d_in[23];
    const float* mlpn_b   = (const float*)d_in[24];
    const float* sem_W1   = (const float*)d_in[25];
    const float* sem_b1   = (const float*)d_in[26];
    const float* sem_W2   = (const float*)d_in[27];
    const float* pred_W   = (const float*)d_in[28];
    const float* pred_b   = (const float*)d_in[29];

    prep_kernel<<<48, 256>>>(Whh);
    fused_kernel<<<NGRU + NCOMP, 64>>>(inputs, Wih, bih, bhh,
                                       pos_W, neg_W, pos_Wu, pos_Wv, neg_Wu, neg_Wv,
                                       pos_adj, neg_adj);
    attn_kernel<<<dim3(NN, 2), 256>>>();
    comb_kernel<<<NN / 8, 128>>>(pos_b, pos_projW, pos_projb, neg_b, neg_projW, neg_projb,
                                 self_W, self_b, mlpp_W, mlpp_b, mlpn_W, mlpn_b,
                                 sem_W1, sem_b1, sem_W2);
    final_kernel<<<NN / 4, 128>>>(pred_W, pred_b, (float*)d_out);
}

// round 12
// speedup vs baseline: 1.0658x; 1.0658x over previous
#include <cuda_runtime.h>

#define NN 3000
#define TT 20
#define IND 6
#define HD 64
#define NH 8
#define MAXNZ 512

// ---------------- scratch (no allocation allowed) ----------------
__device__ ulonglong2 g_Whh4[(HD / 2) * 192];  // [kpair][row] -> (pk(w_k), pk(w_{k+1}))
__device__ float g_support[NN * HD];        // GRU final hidden
__device__ float g_s[2][NN * HD];           // per-graph head features  [n][h*8+f]
__device__ float g_f1[2][NH * NN];          // source scores  [g][h*N+n]
__device__ float g_f2[2][NH * NN];          // dest scores    [g][h*N+n]
__device__ unsigned g_f1maxI[16];           // encoded global per-(g,h) max of f1
__device__ float g_att[2][NN * HD];         // attention outputs
__device__ float g_emb[NN * HD];            // pre-pairnorm embedding
__device__ float g_colsum[HD];              // column sums for pairnorm mean

__device__ __forceinline__ float sigm(float x) { return 1.0f / (1.0f + __expf(-x)); }
__device__ __forceinline__ float tanhfast(float x) { return 2.0f * sigm(2.0f * x) - 1.0f; }

// order-preserving float<->uint encoding for atomicMax
__device__ __forceinline__ unsigned fenc(float f) {
    unsigned u = __float_as_uint(f);
    return (u & 0x80000000u) ? ~u : (u | 0x80000000u);
}
__device__ __forceinline__ float fdec(unsigned u) {
    return __uint_as_float((u & 0x80000000u) ? (u & 0x7fffffffu) : ~u);
}

// packed f32x2 helpers
__device__ __forceinline__ unsigned long long pk(float lo, float hi) {
    unsigned long long r;
    asm("mov.b64 %0, {%1,%2};" : "=l"(r) : "f"(lo), "f"(hi));
    return r;
}
__device__ __forceinline__ void upk(unsigned long long v, float& lo, float& hi) {
    asm("mov.b64 {%0,%1}, %2;" : "=f"(lo), "=f"(hi) : "l"(v));
}
__device__ __forceinline__ void ffma2(unsigned long long& d, unsigned long long a, unsigned long long b) {
    asm("fma.rn.f32x2 %0, %1, %2, %0;" : "+l"(d) : "l"(a), "l"(b));
}

// ---------------- K0: pack Whh into k-pair LDG.128 layout + init reductions ----------------
__global__ void prep_kernel(const float* __restrict__ Whh) {
    int i = blockIdx.x * 256 + threadIdx.x;
    if (i < 192 * HD) {
        int r = i >> 6, k = i & 63;
        float w = Whh[i];
        unsigned long long pw = pk(w, w);
        if (k & 1) g_Whh4[(k >> 1) * 192 + r].y = pw;
        else       g_Whh4[(k >> 1) * 192 + r].x = pw;
    }
    if (blockIdx.x == 0 && threadIdx.x < HD) g_colsum[threadIdx.x] = 0.f;
    if (blockIdx.x == 0 && threadIdx.x < 16) g_f1maxI[threadIdx.x] = 0u;
}

// ---------------- K1: GRU (4 nodes / 64-thread block), x-preload + ping-pong h,
//                  LDG.128 weight loads, fused head projection ----------------
__global__ void __launch_bounds__(64) gru_kernel(
        const float* __restrict__ x, const float* __restrict__ Wih,
        const float* __restrict__ bih, const float* __restrict__ bhh,
        const float* __restrict__ Wp, const float* __restrict__ Wn,
        const float* __restrict__ Wup, const float* __restrict__ Wvp,
        const float* __restrict__ Wun, const float* __restrict__ Wvn) {
    __shared__ float4 shh4[2][HD];      // ping-pong: [buf][k] -> 4 nodes hidden
    __shared__ float shx[TT * IND * 4]; // [ (t*6+c)*4 + b ]
    int j = threadIdx.x;                // gate/hidden index 0..63
    int node0 = blockIdx.x * 4;         // 750 blocks

    // ---- preload all inputs for 4 nodes x 20 steps (coalesced LDGs) ----
#pragma unroll
    for (int e = j; e < TT * IND * 4; e += 64) {
        int b = e / (TT * IND), rem = e % (TT * IND);
        shx[rem * 4 + b] = x[node0 * (TT * IND) + e];
    }

    unsigned long long pwr[IND], pwz[IND], pwn[IND];
#pragma unroll
    for (int c = 0; c < IND; c++) {
        float a = Wih[j * IND + c];
        float b = Wih[(64 + j) * IND + c];
        float d = Wih[(128 + j) * IND + c];
        pwr[c] = pk(a, a); pwz[c] = pk(b, b); pwn[c] = pk(d, d);
    }
    float br  = bih[j] + bhh[j];
    float bz  = bih[64 + j] + bhh[64 + j];
    float bin = bih[128 + j];
    float bhn = bhh[128 + j];
    unsigned long long pbr = pk(br, br), pbz = pk(bz, bz);
    unsigned long long pbi = pk(bin, bin), pbh = pk(bhn, bhn);

    shh4[0][j] = make_float4(0.f, 0.f, 0.f, 0.f);
    float h0 = 0.f, h1 = 0.f, h2 = 0.f, h3 = 0.f;
    int cur = 0;
    __syncthreads();   // shx + zeroed shh visible

    for (int t = 0; t < TT; t++) {
        const float4* xt = (const float4*)(shx + t * IND * 4);

        unsigned long long ar01 = pbr, ar23 = pbr;
        unsigned long long az01 = pbz, az23 = pbz;
        unsigned long long an01 = pbi, an23 = pbi;
        unsigned long long gn01 = pbh, gn23 = pbh;

#pragma unroll
        for (int c = 0; c < IND; c++) {
            float4 xv = xt[c];
            unsigned long long x01 = pk(xv.x, xv.y), x23 = pk(xv.z, xv.w);
            ffma2(ar01, pwr[c], x01); ffma2(ar23, pwr[c], x23);
            ffma2(az01, pwz[c], x01); ffma2(az23, pwz[c], x23);
            ffma2(an01, pwn[c], x01); ffma2(an23, pwn[c], x23);
        }

        const float4* hbuf = shh4[cur];
#pragma unroll 4
        for (int p = 0; p < HD / 2; p++) {
            float4 hva = hbuf[2 * p], hvb = hbuf[2 * p + 1];
            unsigned long long ha01 = pk(hva.x, hva.y), ha23 = pk(hva.z, hva.w);
            unsigned long long hb01 = pk(hvb.x, hvb.y), hb23 = pk(hvb.z, hvb.w);
            ulonglong2 wr = g_Whh4[p * 192 + j];
            ulonglong2 wz = g_Whh4[p * 192 + 64 + j];
            ulonglong2 wn_ = g_Whh4[p * 192 + 128 + j];
            ffma2(ar01, wr.x, ha01);  ffma2(ar23, wr.x, ha23);
            ffma2(az01, wz.x, ha01);  ffma2(az23, wz.x, ha23);
            ffma2(gn01, wn_.x, ha01); ffma2(gn23, wn_.x, ha23);
            ffma2(ar01, wr.y, hb01);  ffma2(ar23, wr.y, hb23);
            ffma2(az01, wz.y, hb01);  ffma2(az23, wz.y, hb23);
            ffma2(gn01, wn_.y, hb01); ffma2(gn23, wn_.y, hb23);
        }

        float a0, a1, a2, a3, z0, z1, z2, z3, n0, n1, n2, n3, g0, g1, g2, g3;
        upk(ar01, a0, a1); upk(ar23, a2, a3);
        upk(az01, z0, z1); upk(az23, z2, z3);
        upk(an01, n0, n1); upk(an23, n2, n3);
        upk(gn01, g0, g1); upk(gn23, g2, g3);

        float r0 = sigm(a0), r1 = sigm(a1), r2 = sigm(a2), r3 = sigm(a3);
        float zz0 = sigm(z0), zz1 = sigm(z1), zz2 = sigm(z2), zz3 = sigm(z3);
        float nv0 = tanhfast(n0 + r0 * g0);
        float nv1 = tanhfast(n1 + r1 * g1);
        float nv2 = tanhfast(n2 + r2 * g2);
        float nv3 = tanhfast(n3 + r3 * g3);
        h0 = (1.f - zz0) * nv0 + zz0 * h0;
        h1 = (1.f - zz1) * nv1 + zz1 * h1;
        h2 = (1.f - zz2) * nv2 + zz2 * h2;
        h3 = (1.f - zz3) * nv3 + zz3 * h3;
        shh4[cur ^ 1][j] = make_float4(h0, h1, h2, h3);
        __syncthreads();   // single barrier: write visibility + read anti-dep
        cur ^= 1;
    }

    g_support[(node0 + 0) * HD + j] = h0;
    g_support[(node0 + 1) * HD + j] = h1;
    g_support[(node0 + 2) * HD + j] = h2;
    g_support[(node0 + 3) * HD + j] = h3;

    // ------ fused head projection: s = h @ W, f1/f2, global f1 max ------
    int hh = j >> 3, f = j & 7;
    const float* hsm = (const float*)shh4[cur];   // [k*4 + b]
#pragma unroll
    for (int g = 0; g < 2; g++) {
        const float* W  = g ? Wn  : Wp;
        float wu = (g ? Wun : Wup)[hh * 8 + f];
        float wv = (g ? Wvn : Wvp)[hh * 8 + f];
        float acc[4] = {0.f, 0.f, 0.f, 0.f};
#pragma unroll 4
        for (int k = 0; k < HD; k++) {
            float w = W[k * HD + j];
#pragma unroll
            for (int b = 0; b < 4; b++) acc[b] += hsm[k * 4 + b] * w;
        }
#pragma unroll
        for (int b = 0; b < 4; b++) {
            int n = node0 + b;
            g_s[g][n * HD + j] = acc[b];
            float t1 = acc[b] * wu, t2 = acc[b] * wv;
#pragma unroll
            for (int o = 4; o; o >>= 1) {
                t1 += __shfl_xor_sync(0xffffffffu, t1, o);
                t2 += __shfl_xor_sync(0xffffffffu, t2, o);
            }
            if (f == 0) {
                g_f1[g][hh * NN + n] = t1;
                g_f2[g][hh * NN + n] = t2;
                atomicMax(&g_f1maxI[g * 8 + hh], fenc(t1));
            }
        }
    }
}

// ---------------- K3: sparse masked attention, atomic-free compaction (grid: [N, 2]) ----------------
__global__ void attn_kernel(const float* __restrict__ adj0, const float* __restrict__ adj1) {
    int i = blockIdx.x, g = blockIdx.y;
    const float* row = (g ? adj1 : adj0) + (size_t)i * NN;
    __shared__ short idx[MAXNZ];
    __shared__ int cnts[8];
    int tid = threadIdx.x, warp = tid >> 5, lane = tid & 31;

    // prefetch the whole row slice to registers (MLP=3)
    const float4* row4 = (const float4*)row;   // N=3000 divisible by 4
    float4 v[3];
#pragma unroll
    for (int it = 0; it < 3; it++) {
        int q = it * 256 + tid;
        v[it] = (q < NN / 4) ? row4[q] : make_float4(0.f, 0.f, 0.f, 0.f);
    }

    // phase A: record ballot masks + per-warp count (no atomics)
    unsigned bal[12];
    int wcnt = 0;
#pragma unroll
    for (int it = 0; it < 3; it++) {
#pragma unroll
        for (int c = 0; c < 4; c++) {
            float val = (c == 0) ? v[it].x : (c == 1) ? v[it].y : (c == 2) ? v[it].z : v[it].w;
            unsigned b = __ballot_sync(0xffffffffu, val != 0.f);
            bal[it * 4 + c] = b;
            wcnt += __popc(b);
        }
    }
    if (lane == 0) cnts[warp] = wcnt;
    __syncthreads();

    // every thread computes its warp's exclusive base + block total
    int base = 0, m = 0;
#pragma unroll
    for (int s = 0; s < 8; s++) {
        int cs = cnts[s];
        if (s < warp) base += cs;
        m += cs;
    }
    m = min(m, MAXNZ);

    // phase B: replay stored masks into exact slots
    unsigned ltmask = (1u << lane) - 1u;
    int off = base;
#pragma unroll
    for (int it = 0; it < 3; it++) {
        int q = it * 256 + tid;
#pragma unroll
        for (int c = 0; c < 4; c++) {
            unsigned b = bal[it * 4 + c];
            if (b) {
                float val = (c == 0) ? v[it].x : (c == 1) ? v[it].y : (c == 2) ? v[it].z : v[it].w;
                if (val != 0.f) {
                    int p = off + __popc(b & ltmask);
                    if (p < MAXNZ) idx[p] = (short)(4 * q + c);
                }
                off += __popc(b);
            }
        }
    }
    __syncthreads();

    int h = warp;                             // warp = head
    const float* f1h = g_f1[g] + h * NN;
    float f2v = g_f2[g][h * NN + i];
    // shift M >= max over row nonzeros (leaky monotone; softmax shift-invariant)
    float Mv = fdec(g_f1maxI[g * 8 + h]) + f2v;
    Mv = Mv >= 0.f ? Mv : 0.2f * Mv;
    const float* sb = g_s[g];

    float se = 0.f;
    float acc[8] = {0, 0, 0, 0, 0, 0, 0, 0};
    for (int k = lane; k < m; k += 32) {
        int jj = idx[k];
        float vv = f1h[jj] + f2v;
        vv = vv >= 0.f ? vv : 0.2f * vv;
        float e = __expf(vv - Mv);
        se += e;
        const float4* sp = (const float4*)(sb + jj * HD + h * 8);
        float4 a = sp[0], bb = sp[1];
        acc[0] += e * a.x;  acc[1] += e * a.y;  acc[2] += e * a.z;  acc[3] += e * a.w;
        acc[4] += e * bb.x; acc[5] += e * bb.y; acc[6] += e * bb.z; acc[7] += e * bb.w;
    }
#pragma unroll
    for (int o = 16; o; o >>= 1) {
        se += __shfl_xor_sync(0xffffffffu, se, o);
#pragma unroll
        for (int f = 0; f < 8; f++) acc[f] += __shfl_xor_sync(0xffffffffu, acc[f], o);
    }
    if (lane == 0) {
        float inv = se > 0.f ? 1.0f / se : 0.f;   // empty row -> zeros (matches ref mask)
        float* o2 = g_att[g] + i * HD + h * 8;
#pragma unroll
        for (int f = 0; f < 8; f++) o2[f] = acc[f] * inv;
    }
}

// ---------------- K4: warp-per-2-nodes, float2 channel pairing (grid: N/8, block 128) ----------------
__global__ void __launch_bounds__(128) comb_kernel(
        const float* __restrict__ pos_b, const float* __restrict__ pWp, const float* __restrict__ pbp,
        const float* __restrict__ neg_b, const float* __restrict__ pWn, const float* __restrict__ pbn,
        const float* __restrict__ selfW, const float* __restrict__ selfb,
        const float* __restrict__ mpW, const float* __restrict__ mpb,
        const float* __restrict__ mnW, const float* __restrict__ mnb,
        const float* __restrict__ semW1, const float* __restrict__ semb1,
        const float* __restrict__ semW2) {
    __shared__ float sb[4][12][HD];     // per-warp staging
    __shared__ float colacc[HD];
    int tid = threadIdx.x, warp = tid >> 5, lane = tid & 31;
    int nA = blockIdx.x * 8 + warp * 2;   // 375*8 = 3000 exact
    int nB = nA + 1;
    int c0 = 2 * lane, c1 = 2 * lane + 1;

    if (tid < HD) colacc[tid] = 0.f;
    __syncthreads();

    const float2* pWp2 = (const float2*)pWp;
    const float2* pWn2 = (const float2*)pWn;
    const float2* sfW2 = (const float2*)selfW;
    const float2* mpW2 = (const float2*)mpW;
    const float2* mnW2 = (const float2*)mnW;
    const float2* sm12 = (const float2*)semW1;

    float (*S)[HD] = sb[warp];
    {
        float2 sA = ((const float2*)(g_support + nA * HD))[lane];
        float2 sB = ((const float2*)(g_support + nB * HD))[lane];
        S[0][c0] = sA.x; S[0][c1] = sA.y;
        S[1][c0] = sB.x; S[1][c1] = sB.y;
    }
    __syncwarp();

    // ---- phase 1 ----
    float2 pb2  = ((const float2*)pos_b)[lane];
    float2 pbp2 = ((const float2*)pbp)[lane];
    float2 nb2  = ((const float2*)neg_b)[lane];
    float2 pbn2 = ((const float2*)pbn)[lane];
    float2 sfb2 = ((const float2*)selfb)[lane];
    float2 atpA = ((const float2*)(g_att[0] + nA * HD))[lane];
    float2 atpB = ((const float2*)(g_att[0] + nB * HD))[lane];
    float2 atnA = ((const float2*)(g_att[1] + nA * HD))[lane];
    float2 atnB = ((const float2*)(g_att[1] + nB * HD))[lane];
    float apA0 = atpA.x + pb2.x + pbp2.x, apA1 = atpA.y + pb2.y + pbp2.y;
    float apB0 = atpB.x + pb2.x + pbp2.x, apB1 = atpB.y + pb2.y + pbp2.y;
    float anA0 = atnA.x + nb2.x + pbn2.x, anA1 = atnA.y + nb2.y + pbn2.y;
    float anB0 = atnB.x + nb2.x + pbn2.x, anB1 = atnB.y + nb2.y + pbn2.y;
    float svA0 = sfb2.x, svA1 = sfb2.y, svB0 = sfb2.x, svB1 = sfb2.y;
#pragma unroll 8
    for (int k = 0; k < HD; k++) {
        float sA = S[0][k], sBv = S[1][k];
        float2 wp = pWp2[k * 32 + lane];
        float2 wn = pWn2[k * 32 + lane];
        float2 ws = sfW2[k * 32 + lane];
        apA0 += sA * wp.x;  apA1 += sA * wp.y;  apB0 += sBv * wp.x;  apB1 += sBv * wp.y;
        anA0 += sA * wn.x;  anA1 += sA * wn.y;  anB0 += sBv * wn.x;  anB1 += sBv * wn.y;
        svA0 += sA * ws.x;  svA1 += sA * ws.y;  svB0 += sBv * ws.x;  svB1 += sBv * ws.y;
    }
    S[2][c0] = apA0; S[2][c1] = apA1; S[3][c0] = apB0; S[3][c1] = apB1;
    S[4][c0] = anA0; S[4][c1] = anA1; S[5][c0] = anB0; S[5][c1] = anB1;
    __syncwarp();

    // ---- phase 2 ----
    float2 mpb2 = ((const float2*)mpb)[lane];
    float2 mnb2 = ((const float2*)mnb)[lane];
    float spA0 = mpb2.x, spA1 = mpb2.y, spB0 = mpb2.x, spB1 = mpb2.y;
    float snA0 = mnb2.x, snA1 = mnb2.y, snB0 = mnb2.x, snB1 = mnb2.y;
#pragma unroll 8
    for (int k = 0; k < HD; k++) {
        float pA = S[2][k], pB = S[3][k], qA = S[4][k], qB = S[5][k];
        float2 w = mpW2[k * 32 + lane];
        float2 v = mnW2[k * 32 + lane];
        spA0 += pA * w.x; spA1 += pA * w.y; spB0 += pB * w.x; spB1 += pB * w.y;
        snA0 += qA * v.x; snA1 += qA * v.y; snB0 += qB * v.x; snB1 += qB * v.y;
    }
    S[6][c0] = svA0; S[6][c1] = svA1; S[7][c0] = svB0; S[7][c1] = svB1;
    S[8][c0] = spA0; S[8][c1] = spA1; S[9][c0] = spB0; S[9][c1] = spB1;
    S[10][c0] = snA0; S[10][c1] = snA1; S[11][c0] = snB0; S[11][c1] = snB1;
    __syncwarp();

    // ---- phase 3: semantic attention logits ----
    float2 sb12 = ((const float2*)semb1)[lane];
    float tA00 = sb12.x, tA01 = sb12.y, tA10 = sb12.x, tA11 = sb12.y, tA20 = sb12.x, tA21 = sb12.y;
    float tB00 = sb12.x, tB01 = sb12.y, tB10 = sb12.x, tB11 = sb12.y, tB20 = sb12.x, tB21 = sb12.y;
#pragma unroll 8
    for (int k = 0; k < HD; k++) {
        float2 w = sm12[k * 32 + lane];
        float e0A = S[6][k], e0B = S[7][k];
        float e1A = S[8][k], e1B = S[9][k];
        float e2A = S[10][k], e2B = S[11][k];
        tA00 += e0A * w.x; tA01 += e0A * w.y; tB00 += e0B * w.x; tB01 += e0B * w.y;
        tA10 += e1A * w.x; tA11 += e1A * w.y; tB10 += e1B * w.x; tB11 += e1B * w.y;
        tA20 += e2A * w.x; tA21 += e2A * w.y; tB20 += e2B * w.x; tB21 += e2B * w.y;
    }
    float2 w22 = ((const float2*)semW2)[lane];
    float uA0 = tanhfast(tA00) * w22.x + tanhfast(tA01) * w22.y;
    float uA1 = tanhfast(tA10) * w22.x + tanhfast(tA11) * w22.y;
    float uA2 = tanhfast(tA20) * w22.x + tanhfast(tA21) * w22.y;
    float uB0 = tanhfast(tB00) * w22.x + tanhfast(tB01) * w22.y;
    float uB1 = tanhfast(tB10) * w22.x + tanhfast(tB11) * w22.y;
    float uB2 = tanhfast(tB20) * w22.x + tanhfast(tB21) * w22.y;
#pragma unroll
    for (int o = 16; o; o >>= 1) {
        uA0 += __shfl_xor_sync(0xffffffffu, uA0, o);
        uA1 += __shfl_xor_sync(0xffffffffu, uA1, o);
        uA2 += __shfl_xor_sync(0xffffffffu, uA2, o);
        uB0 += __shfl_xor_sync(0xffffffffu, uB0, o);
        uB1 += __shfl_xor_sync(0xffffffffu, uB1, o);
        uB2 += __shfl_xor_sync(0xffffffffu, uB2, o);
    }
    float mA = fmaxf(uA0, fmaxf(uA1, uA2));
    float eA0 = __expf(uA0 - mA), eA1 = __expf(uA1 - mA), eA2 = __expf(uA2 - mA);
    float invA = 1.f / (eA0 + eA1 + eA2);
    float embA0 = (eA0 * svA0 + eA1 * spA0 + eA2 * snA0) * invA;
    float embA1 = (eA0 * svA1 + eA1 * spA1 + eA2 * snA1) * invA;
    float mB = fmaxf(uB0, fmaxf(uB1, uB2));
    float eB0 = __expf(uB0 - mB), eB1 = __expf(uB1 - mB), eB2 = __expf(uB2 - mB);
    float invB = 1.f / (eB0 + eB1 + eB2);
    float embB0 = (eB0 * svB0 + eB1 * spB0 + eB2 * snB0) * invB;
    float embB1 = (eB0 * svB1 + eB1 * spB1 + eB2 * snB1) * invB;

    ((float2*)(g_emb + nA * HD))[lane] = make_float2(embA0, embA1);
    ((float2*)(g_emb + nB * HD))[lane] = make_float2(embB0, embB1);
    atomicAdd(&colacc[c0], embA0 + embB0);
    atomicAdd(&colacc[c1], embA1 + embB1);
    __syncthreads();
    if (tid < HD) atomicAdd(&g_colsum[tid], colacc[tid]);
}

// ---------------- K5: pairnorm + prediction head (warp per node) ----------------
__global__ void final_kernel(const float* __restrict__ predW, const float* __restrict__ predb,
                             float* __restrict__ out) {
    int warp = threadIdx.x >> 5, lane = threadIdx.x & 31;
    int n = blockIdx.x * 4 + warp;
    float invn = 1.0f / NN;
    float x0 = g_emb[n * HD + lane]      - g_colsum[lane]      * invn;
    float x1 = g_emb[n * HD + 32 + lane] - g_colsum[32 + lane] * invn;
    float ss = x0 * x0 + x1 * x1;
    float dt = x0 * predW[lane] + x1 * predW[32 + lane];
#pragma unroll
    for (int o = 16; o; o >>= 1) {
        ss += __shfl_xor_sync(0xffffffffu, ss, o);
        dt += __shfl_xor_sync(0xffffffffu, dt, o);
    }
    if (lane == 0) out[n] = sigm(dt * rsqrtf(1e-6f + ss) + predb[0]);
}

// ---------------- launch ----------------
extern "C" void kernel_launch(void* const* d_in, const int* in_sizes, int n_in,
                              void* d_out, int out_size) {
    (void)in_sizes; (void)n_in; (void)out_size;
    const float* inputs   = (const float*)d_in[0];
    const float* pos_adj  = (const float*)d_in[1];
    const float* neg_adj  = (const float*)d_in[2];
    const float* Wih      = (const float*)d_in[3];
    const float* Whh      = (const float*)d_in[4];
    const float* bih      = (const float*)d_in[5];
    const float* bhh      = (const float*)d_in[6];
    const float* pos_W    = (const float*)d_in[7];
    const float* pos_Wu   = (const float*)d_in[8];
    const float* pos_Wv   = (const float*)d_in[9];
    const float* pos_b    = (const float*)d_in[10];
    const float* pos_projW= (const float*)d_in[11];
    const float* pos_projb= (const float*)d_in[12];
    const float* neg_W    = (const float*)d_in[13];
    const float* neg_Wu   = (const float*)d_in[14];
    const float* neg_Wv   = (const float*)d_in[15];
    const float* neg_b    = (const float*)d_in[16];
    const float* neg_projW= (const float*)d_in[17];
    const float* neg_projb= (const float*)d_in[18];
    const float* self_W   = (const float*)d_in[19];
    const float* self_b   = (const float*)d_in[20];
    const float* mlpp_W   = (const float*)d_in[21];
    const float* mlpp_b   = (const float*)d_in[22];
    const float* mlpn_W   = (const float*)d_in[23];
    const float* mlpn_b   = (const float*)d_in[24];
    const float* sem_W1   = (const float*)d_in[25];
    const float* sem_b1   = (const float*)d_in[26];
    const float* sem_W2   = (const float*)d_in[27];
    const float* pred_W   = (const float*)d_in[28];
    const float* pred_b   = (const float*)d_in[29];

    prep_kernel<<<48, 256>>>(Whh);
    gru_kernel<<<NN / 4, 64>>>(inputs, Wih, bih, bhh,
                               pos_W, neg_W, pos_Wu, pos_Wv, neg_Wu, neg_Wv);
    attn_kernel<<<dim3(NN, 2), 256>>>(pos_adj, neg_adj);
    comb_kernel<<<NN / 8, 128>>>(pos_b, pos_projW, pos_projb, neg_b, neg_projW, neg_projb,
                                 self_W, self_b, mlpp_W, mlpp_b, mlpn_W, mlpn_b,
                                 sem_W1, sem_b1, sem_W2);
    final_kernel<<<NN / 4, 128>>>(pred_W, pred_b, (float*)d_out);
}

// round 13
// speedup vs baseline: 1.0795x; 1.0129x over previous
#include <cuda_runtime.h>

#define NN 3000
#define TT 20
#define IND 6
#define HD 64
#define NH 8
#define MAXNZ 512

// ---------------- scratch (no allocation allowed) ----------------
__device__ ulonglong2 g_Whh4[(HD / 2) * 192];  // [kpair][row] -> (pk(w_k), pk(w_{k+1}))
__device__ float g_support[NN * HD];        // GRU final hidden
__device__ float g_s[2][NN * HD];           // per-graph head features  [n][h*8+f]
__device__ float g_f1[2][NH * NN];          // source scores  [g][h*N+n]
__device__ float g_f2[2][NH * NN];          // dest scores    [g][h*N+n]
__device__ unsigned g_f1maxI[16];           // encoded global per-(g,h) max of f1
__device__ float g_att[2][NN * HD];         // attention outputs
__device__ float g_emb[NN * HD];            // pre-pairnorm embedding
__device__ float g_colsum[HD];              // column sums for pairnorm mean

__device__ __forceinline__ float sigm(float x) { return 1.0f / (1.0f + __expf(-x)); }
__device__ __forceinline__ float tanhfast(float x) { return 2.0f * sigm(2.0f * x) - 1.0f; }

// order-preserving float<->uint encoding for atomicMax
__device__ __forceinline__ unsigned fenc(float f) {
    unsigned u = __float_as_uint(f);
    return (u & 0x80000000u) ? ~u : (u | 0x80000000u);
}
__device__ __forceinline__ float fdec(unsigned u) {
    return __uint_as_float((u & 0x80000000u) ? (u & 0x7fffffffu) : ~u);
}

// packed f32x2 helpers
__device__ __forceinline__ unsigned long long pk(float lo, float hi) {
    unsigned long long r;
    asm("mov.b64 %0, {%1,%2};" : "=l"(r) : "f"(lo), "f"(hi));
    return r;
}
__device__ __forceinline__ void upk(unsigned long long v, float& lo, float& hi) {
    asm("mov.b64 {%0,%1}, %2;" : "=f"(lo), "=f"(hi) : "l"(v));
}
__device__ __forceinline__ void ffma2(unsigned long long& d, unsigned long long a, unsigned long long b) {
    asm("fma.rn.f32x2 %0, %1, %2, %0;" : "+l"(d) : "l"(a), "l"(b));
}

// ---------------- K0: pack Whh into k-pair LDG.128 layout + init reductions ----------------
__global__ void prep_kernel(const float* __restrict__ Whh) {
    int i = blockIdx.x * 256 + threadIdx.x;
    if (i < 192 * HD) {
        int r = i >> 6, k = i & 63;
        float w = Whh[i];
        unsigned long long pw = pk(w, w);
        if (k & 1) g_Whh4[(k >> 1) * 192 + r].y = pw;
        else       g_Whh4[(k >> 1) * 192 + r].x = pw;
    }
    if (blockIdx.x == 0 && threadIdx.x < HD) g_colsum[threadIdx.x] = 0.f;
    if (blockIdx.x == 0 && threadIdx.x < 16) g_f1maxI[threadIdx.x] = 0u;
}

// ---------------- K1: GRU (4 nodes / 64-thread block), x-preload + ping-pong h,
//                  LDG.128 weight loads, fused head projection, PDL over prep ----------------
__global__ void __launch_bounds__(64) gru_kernel(
        const float* __restrict__ x, const float* __restrict__ Wih,
        const float* __restrict__ bih, const float* __restrict__ bhh,
        const float* __restrict__ Wp, const float* __restrict__ Wn,
        const float* __restrict__ Wup, const float* __restrict__ Wvp,
        const float* __restrict__ Wun, const float* __restrict__ Wvn) {
    __shared__ float4 shh4[2][HD];      // ping-pong: [buf][k] -> 4 nodes hidden
    __shared__ float shx[TT * IND * 4]; // [ (t*6+c)*4 + b ]
    int j = threadIdx.x;                // gate/hidden index 0..63
    int node0 = blockIdx.x * 4;         // 750 blocks

    // ---- prologue independent of prep: preload x, Wih, biases ----
#pragma unroll
    for (int e = j; e < TT * IND * 4; e += 64) {
        int b = e / (TT * IND), rem = e % (TT * IND);
        shx[rem * 4 + b] = x[node0 * (TT * IND) + e];
    }

    unsigned long long pwr[IND], pwz[IND], pwn[IND];
#pragma unroll
    for (int c = 0; c < IND; c++) {
        float a = Wih[j * IND + c];
        float b = Wih[(64 + j) * IND + c];
        float d = Wih[(128 + j) * IND + c];
        pwr[c] = pk(a, a); pwz[c] = pk(b, b); pwn[c] = pk(d, d);
    }
    float br  = bih[j] + bhh[j];
    float bz  = bih[64 + j] + bhh[64 + j];
    float bin = bih[128 + j];
    float bhn = bhh[128 + j];
    unsigned long long pbr = pk(br, br), pbz = pk(bz, bz);
    unsigned long long pbi = pk(bin, bin), pbh = pk(bhn, bhn);

    shh4[0][j] = make_float4(0.f, 0.f, 0.f, 0.f);
    float h0 = 0.f, h1 = 0.f, h2 = 0.f, h3 = 0.f;
    int cur = 0;

    cudaGridDependencySynchronize();    // g_Whh4 / g_colsum / g_f1maxI ready (prep done)
    __syncthreads();   // shx + zeroed shh visible

    for (int t = 0; t < TT; t++) {
        const float4* xt = (const float4*)(shx + t * IND * 4);

        unsigned long long ar01 = pbr, ar23 = pbr;
        unsigned long long az01 = pbz, az23 = pbz;
        unsigned long long an01 = pbi, an23 = pbi;
        unsigned long long gn01 = pbh, gn23 = pbh;

#pragma unroll
        for (int c = 0; c < IND; c++) {
            float4 xv = xt[c];
            unsigned long long x01 = pk(xv.x, xv.y), x23 = pk(xv.z, xv.w);
            ffma2(ar01, pwr[c], x01); ffma2(ar23, pwr[c], x23);
            ffma2(az01, pwz[c], x01); ffma2(az23, pwz[c], x23);
            ffma2(an01, pwn[c], x01); ffma2(an23, pwn[c], x23);
        }

        const float4* hbuf = shh4[cur];
#pragma unroll 4
        for (int p = 0; p < HD / 2; p++) {
            float4 hva = hbuf[2 * p], hvb = hbuf[2 * p + 1];
            unsigned long long ha01 = pk(hva.x, hva.y), ha23 = pk(hva.z, hva.w);
            unsigned long long hb01 = pk(hvb.x, hvb.y), hb23 = pk(hvb.z, hvb.w);
            ulonglong2 wr = g_Whh4[p * 192 + j];
            ulonglong2 wz = g_Whh4[p * 192 + 64 + j];
            ulonglong2 wn_ = g_Whh4[p * 192 + 128 + j];
            ffma2(ar01, wr.x, ha01);  ffma2(ar23, wr.x, ha23);
            ffma2(az01, wz.x, ha01);  ffma2(az23, wz.x, ha23);
            ffma2(gn01, wn_.x, ha01); ffma2(gn23, wn_.x, ha23);
            ffma2(ar01, wr.y, hb01);  ffma2(ar23, wr.y, hb23);
            ffma2(az01, wz.y, hb01);  ffma2(az23, wz.y, hb23);
            ffma2(gn01, wn_.y, hb01); ffma2(gn23, wn_.y, hb23);
        }

        float a0, a1, a2, a3, z0, z1, z2, z3, n0, n1, n2, n3, g0, g1, g2, g3;
        upk(ar01, a0, a1); upk(ar23, a2, a3);
        upk(az01, z0, z1); upk(az23, z2, z3);
        upk(an01, n0, n1); upk(an23, n2, n3);
        upk(gn01, g0, g1); upk(gn23, g2, g3);

        float r0 = sigm(a0), r1 = sigm(a1), r2 = sigm(a2), r3 = sigm(a3);
        float zz0 = sigm(z0), zz1 = sigm(z1), zz2 = sigm(z2), zz3 = sigm(z3);
        float nv0 = tanhfast(n0 + r0 * g0);
        float nv1 = tanhfast(n1 + r1 * g1);
        float nv2 = tanhfast(n2 + r2 * g2);
        float nv3 = tanhfast(n3 + r3 * g3);
        h0 = (1.f - zz0) * nv0 + zz0 * h0;
        h1 = (1.f - zz1) * nv1 + zz1 * h1;
        h2 = (1.f - zz2) * nv2 + zz2 * h2;
        h3 = (1.f - zz3) * nv3 + zz3 * h3;
        shh4[cur ^ 1][j] = make_float4(h0, h1, h2, h3);
        __syncthreads();   // single barrier: write visibility + read anti-dep
        cur ^= 1;
    }

    g_support[(node0 + 0) * HD + j] = h0;
    g_support[(node0 + 1) * HD + j] = h1;
    g_support[(node0 + 2) * HD + j] = h2;
    g_support[(node0 + 3) * HD + j] = h3;

    // ------ fused head projection: s = h @ W, f1/f2, global f1 max ------
    int hh = j >> 3, f = j & 7;
    const float* hsm = (const float*)shh4[cur];   // [k*4 + b]
#pragma unroll
    for (int g = 0; g < 2; g++) {
        const float* W  = g ? Wn  : Wp;
        float wu = (g ? Wun : Wup)[hh * 8 + f];
        float wv = (g ? Wvn : Wvp)[hh * 8 + f];
        float acc[4] = {0.f, 0.f, 0.f, 0.f};
#pragma unroll 4
        for (int k = 0; k < HD; k++) {
            float w = W[k * HD + j];
#pragma unroll
            for (int b = 0; b < 4; b++) acc[b] += hsm[k * 4 + b] * w;
        }
#pragma unroll
        for (int b = 0; b < 4; b++) {
            int n = node0 + b;
            g_s[g][n * HD + j] = acc[b];
            float t1 = acc[b] * wu, t2 = acc[b] * wv;
#pragma unroll
            for (int o = 4; o; o >>= 1) {
                t1 += __shfl_xor_sync(0xffffffffu, t1, o);
                t2 += __shfl_xor_sync(0xffffffffu, t2, o);
            }
            if (f == 0) {
                g_f1[g][hh * NN + n] = t1;
                g_f2[g][hh * NN + n] = t2;
                atomicMax(&g_f1maxI[g * 8 + hh], fenc(t1));
            }
        }
    }
}

// ---------------- K3: sparse masked attention; scan+compaction overlapped with GRU via PDL ----------------
__global__ void attn_kernel(const float* __restrict__ adj0, const float* __restrict__ adj1) {
    int i = blockIdx.x, g = blockIdx.y;
    const float* row = (g ? adj1 : adj0) + (size_t)i * NN;
    __shared__ short idx[MAXNZ];
    __shared__ int cnts[8];
    int tid = threadIdx.x, warp = tid >> 5, lane = tid & 31;

    // ===== pre-sync phase: depends only on the adjacency input =====
    const float4* row4 = (const float4*)row;   // N=3000 divisible by 4
    float4 v[3];
#pragma unroll
    for (int it = 0; it < 3; it++) {
        int q = it * 256 + tid;
        v[it] = (q < NN / 4) ? row4[q] : make_float4(0.f, 0.f, 0.f, 0.f);
    }

    // phase A: record ballot masks + per-warp count (no atomics)
    unsigned bal[12];
    int wcnt = 0;
#pragma unroll
    for (int it = 0; it < 3; it++) {
#pragma unroll
        for (int c = 0; c < 4; c++) {
            float val = (c == 0) ? v[it].x : (c == 1) ? v[it].y : (c == 2) ? v[it].z : v[it].w;
            unsigned b = __ballot_sync(0xffffffffu, val != 0.f);
            bal[it * 4 + c] = b;
            wcnt += __popc(b);
        }
    }
    if (lane == 0) cnts[warp] = wcnt;
    __syncthreads();

    int base = 0, m = 0;
#pragma unroll
    for (int s = 0; s < 8; s++) {
        int cs = cnts[s];
        if (s < warp) base += cs;
        m += cs;
    }
    m = min(m, MAXNZ);

    // phase B: replay stored masks into exact slots
    unsigned ltmask = (1u << lane) - 1u;
    int off = base;
#pragma unroll
    for (int it = 0; it < 3; it++) {
        int q = it * 256 + tid;
#pragma unroll
        for (int c = 0; c < 4; c++) {
            unsigned b = bal[it * 4 + c];
            if (b) {
                float val = (c == 0) ? v[it].x : (c == 1) ? v[it].y : (c == 2) ? v[it].z : v[it].w;
                if (val != 0.f) {
                    int p = off + __popc(b & ltmask);
                    if (p < MAXNZ) idx[p] = (short)(4 * q + c);
                }
                off += __popc(b);
            }
        }
    }
    __syncthreads();

    // ===== wait for GRU outputs (f1/f2/s/f1max), then gather =====
    cudaGridDependencySynchronize();

    int h = warp;                             // warp = head
    const float* f1h = g_f1[g] + h * NN;
    float f2v = g_f2[g][h * NN + i];
    // shift M >= max over row nonzeros (leaky monotone; softmax shift-invariant)
    float Mv = fdec(g_f1maxI[g * 8 + h]) + f2v;
    Mv = Mv >= 0.f ? Mv : 0.2f * Mv;
    const float* sb = g_s[g];

    float se = 0.f;
    float acc[8] = {0, 0, 0, 0, 0, 0, 0, 0};
    for (int k = lane; k < m; k += 32) {
        int jj = idx[k];
        float vv = f1h[jj] + f2v;
        vv = vv >= 0.f ? vv : 0.2f * vv;
        float e = __expf(vv - Mv);
        se += e;
        const float4* sp = (const float4*)(sb + jj * HD + h * 8);
        float4 a = sp[0], bb = sp[1];
        acc[0] += e * a.x;  acc[1] += e * a.y;  acc[2] += e * a.z;  acc[3] += e * a.w;
        acc[4] += e * bb.x; acc[5] += e * bb.y; acc[6] += e * bb.z; acc[7] += e * bb.w;
    }
#pragma unroll
    for (int o = 16; o; o >>= 1) {
        se += __shfl_xor_sync(0xffffffffu, se, o);
#pragma unroll
        for (int f = 0; f < 8; f++) acc[f] += __shfl_xor_sync(0xffffffffu, acc[f], o);
    }
    if (lane == 0) {
        float inv = se > 0.f ? 1.0f / se : 0.f;   // empty row -> zeros (matches ref mask)
        float* o2 = g_att[g] + i * HD + h * 8;
#pragma unroll
        for (int f = 0; f < 8; f++) o2[f] = acc[f] * inv;
    }
}

// ---------------- K4: warp-per-2-nodes, float2 channel pairing; PDL over attn ----------------
__global__ void __launch_bounds__(128) comb_kernel(
        const float* __restrict__ pos_b, const float* __restrict__ pWp, const float* __restrict__ pbp,
        const float* __restrict__ neg_b, const float* __restrict__ pWn, const float* __restrict__ pbn,
        const float* __restrict__ selfW, const float* __restrict__ selfb,
        const float* __restrict__ mpW, const float* __restrict__ mpb,
        const float* __restrict__ mnW, const float* __restrict__ mnb,
        const float* __restrict__ semW1, const float* __restrict__ semb1,
        const float* __restrict__ semW2) {
    __shared__ float sb[4][12][HD];     // per-warp staging
    __shared__ float colacc[HD];
    int tid = threadIdx.x, warp = tid >> 5, lane = tid & 31;
    int nA = blockIdx.x * 8 + warp * 2;   // 375*8 = 3000 exact
    int nB = nA + 1;
    int c0 = 2 * lane, c1 = 2 * lane + 1;

    if (tid < HD) colacc[tid] = 0.f;

    const float2* pWp2 = (const float2*)pWp;
    const float2* pWn2 = (const float2*)pWn;
    const float2* sfW2 = (const float2*)selfW;
    const float2* mpW2 = (const float2*)mpW;
    const float2* mnW2 = (const float2*)mnW;
    const float2* sm12 = (const float2*)semW1;

    float (*S)[HD] = sb[warp];
    // prologue: support + biases (gru outputs — already complete before attn ran)
    {
        float2 sA = ((const float2*)(g_support + nA * HD))[lane];
        float2 sB = ((const float2*)(g_support + nB * HD))[lane];
        S[0][c0] = sA.x; S[0][c1] = sA.y;
        S[1][c0] = sB.x; S[1][c1] = sB.y;
    }
    float2 pb2  = ((const float2*)pos_b)[lane];
    float2 pbp2 = ((const float2*)pbp)[lane];
    float2 nb2  = ((const float2*)neg_b)[lane];
    float2 pbn2 = ((const float2*)pbn)[lane];
    float2 sfb2 = ((const float2*)selfb)[lane];
    __syncthreads();

    // wait for attn outputs before reading g_att
    cudaGridDependencySynchronize();

    float2 atpA = ((const float2*)(g_att[0] + nA * HD))[lane];
    float2 atpB = ((const float2*)(g_att[0] + nB * HD))[lane];
    float2 atnA = ((const float2*)(g_att[1] + nA * HD))[lane];
    float2 atnB = ((const float2*)(g_att[1] + nB * HD))[lane];
    float apA0 = atpA.x + pb2.x + pbp2.x, apA1 = atpA.y + pb2.y + pbp2.y;
    float apB0 = atpB.x + pb2.x + pbp2.x, apB1 = atpB.y + pb2.y + pbp2.y;
    float anA0 = atnA.x + nb2.x + pbn2.x, anA1 = atnA.y + nb2.y + pbn2.y;
    float anB0 = atnB.x + nb2.x + pbn2.x, anB1 = atnB.y + nb2.y + pbn2.y;
    float svA0 = sfb2.x, svA1 = sfb2.y, svB0 = sfb2.x, svB1 = sfb2.y;
#pragma unroll 8
    for (int k = 0; k < HD; k++) {
        float sA = S[0][k], sBv = S[1][k];
        float2 wp = pWp2[k * 32 + lane];
        float2 wn = pWn2[k * 32 + lane];
        float2 ws = sfW2[k * 32 + lane];
        apA0 += sA * wp.x;  apA1 += sA * wp.y;  apB0 += sBv * wp.x;  apB1 += sBv * wp.y;
        anA0 += sA * wn.x;  anA1 += sA * wn.y;  anB0 += sBv * wn.x;  anB1 += sBv * wn.y;
        svA0 += sA * ws.x;  svA1 += sA * ws.y;  svB0 += sBv * ws.x;  svB1 += sBv * ws.y;
    }
    S[2][c0] = apA0; S[2][c1] = apA1; S[3][c0] = apB0; S[3][c1] = apB1;
    S[4][c0] = anA0; S[4][c1] = anA1; S[5][c0] = anB0; S[5][c1] = anB1;
    __syncwarp();

    // ---- phase 2 ----
    float2 mpb2 = ((const float2*)mpb)[lane];
    float2 mnb2 = ((const float2*)mnb)[lane];
    float spA0 = mpb2.x, spA1 = mpb2.y, spB0 = mpb2.x, spB1 = mpb2.y;
    float snA0 = mnb2.x, snA1 = mnb2.y, snB0 = mnb2.x, snB1 = mnb2.y;
#pragma unroll 8
    for (int k = 0; k < HD; k++) {
        float pA = S[2][k], pB = S[3][k], qA = S[4][k], qB = S[5][k];
        float2 w = mpW2[k * 32 + lane];
        float2 v = mnW2[k * 32 + lane];
        spA0 += pA * w.x; spA1 += pA * w.y; spB0 += pB * w.x; spB1 += pB * w.y;
        snA0 += qA * v.x; snA1 += qA * v.y; snB0 += qB * v.x; snB1 += qB * v.y;
    }
    S[6][c0] = svA0; S[6][c1] = svA1; S[7][c0] = svB0; S[7][c1] = svB1;
    S[8][c0] = spA0; S[8][c1] = spA1; S[9][c0] = spB0; S[9][c1] = spB1;
    S[10][c0] = snA0; S[10][c1] = snA1; S[11][c0] = snB0; S[11][c1] = snB1;
    __syncwarp();

    // ---- phase 3: semantic attention logits ----
    float2 sb12 = ((const float2*)semb1)[lane];
    float tA00 = sb12.x, tA01 = sb12.y, tA10 = sb12.x, tA11 = sb12.y, tA20 = sb12.x, tA21 = sb12.y;
    float tB00 = sb12.x, tB01 = sb12.y, tB10 = sb12.x, tB11 = sb12.y, tB20 = sb12.x, tB21 = sb12.y;
#pragma unroll 8
    for (int k = 0; k < HD; k++) {
        float2 w = sm12[k * 32 + lane];
        float e0A = S[6][k], e0B = S[7][k];
        float e1A = S[8][k], e1B = S[9][k];
        float e2A = S[10][k], e2B = S[11][k];
        tA00 += e0A * w.x; tA01 += e0A * w.y; tB00 += e0B * w.x; tB01 += e0B * w.y;
        tA10 += e1A * w.x; tA11 += e1A * w.y; tB10 += e1B * w.x; tB11 += e1B * w.y;
        tA20 += e2A * w.x; tA21 += e2A * w.y; tB20 += e2B * w.x; tB21 += e2B * w.y;
    }
    float2 w22 = ((const float2*)semW2)[lane];
    float uA0 = tanhfast(tA00) * w22.x + tanhfast(tA01) * w22.y;
    float uA1 = tanhfast(tA10) * w22.x + tanhfast(tA11) * w22.y;
    float uA2 = tanhfast(tA20) * w22.x + tanhfast(tA21) * w22.y;
    float uB0 = tanhfast(tB00) * w22.x + tanhfast(tB01) * w22.y;
    float uB1 = tanhfast(tB10) * w22.x + tanhfast(tB11) * w22.y;
    float uB2 = tanhfast(tB20) * w22.x + tanhfast(tB21) * w22.y;
#pragma unroll
    for (int o = 16; o; o >>= 1) {
        uA0 += __shfl_xor_sync(0xffffffffu, uA0, o);
        uA1 += __shfl_xor_sync(0xffffffffu, uA1, o);
        uA2 += __shfl_xor_sync(0xffffffffu, uA2, o);
        uB0 += __shfl_xor_sync(0xffffffffu, uB0, o);
        uB1 += __shfl_xor_sync(0xffffffffu, uB1, o);
        uB2 += __shfl_xor_sync(0xffffffffu, uB2, o);
    }
    float mA = fmaxf(uA0, fmaxf(uA1, uA2));
    float eA0 = __expf(uA0 - mA), eA1 = __expf(uA1 - mA), eA2 = __expf(uA2 - mA);
    float invA = 1.f / (eA0 + eA1 + eA2);
    float embA0 = (eA0 * svA0 + eA1 * spA0 + eA2 * snA0) * invA;
    float embA1 = (eA0 * svA1 + eA1 * spA1 + eA2 * snA1) * invA;
    float mB = fmaxf(uB0, fmaxf(uB1, uB2));
    float eB0 = __expf(uB0 - mB), eB1 = __expf(uB1 - mB), eB2 = __expf(uB2 - mB);
    float invB = 1.f / (eB0 + eB1 + eB2);
    float embB0 = (eB0 * svB0 + eB1 * spB0 + eB2 * snB0) * invB;
    float embB1 = (eB0 * svB1 + eB1 * spB1 + eB2 * snB1) * invB;

    ((float2*)(g_emb + nA * HD))[lane] = make_float2(embA0, embA1);
    ((float2*)(g_emb + nB * HD))[lane] = make_float2(embB0, embB1);
    atomicAdd(&colacc[c0], embA0 + embB0);
    atomicAdd(&colacc[c1], embA1 + embB1);
    __syncthreads();
    if (tid < HD) atomicAdd(&g_colsum[tid], colacc[tid]);
}

// ---------------- K5: pairnorm + prediction head (warp per node) ----------------
__global__ void final_kernel(const float* __restrict__ predW, const float* __restrict__ predb,
                             float* __restrict__ out) {
    int warp = threadIdx.x >> 5, lane = threadIdx.x & 31;
    int n = blockIdx.x * 4 + warp;
    float invn = 1.0f / NN;
    float x0 = g_emb[n * HD + lane]      - g_colsum[lane]      * invn;
    float x1 = g_emb[n * HD + 32 + lane] - g_colsum[32 + lane] * invn;
    float ss = x0 * x0 + x1 * x1;
    float dt = x0 * predW[lane] + x1 * predW[32 + lane];
#pragma unroll
    for (int o = 16; o; o >>= 1) {
        ss += __shfl_xor_sync(0xffffffffu, ss, o);
        dt += __shfl_xor_sync(0xffffffffu, dt, o);
    }
    if (lane == 0) out[n] = sigm(dt * rsqrtf(1e-6f + ss) + predb[0]);
}

// ---------------- launch (PDL on gru/attn/comb) ----------------
template <typename... Args>
static void launch_pdl(void (*kern)(Args...), dim3 grid, dim3 block, Args... args) {
    cudaLaunchConfig_t cfg = {};
    cfg.gridDim = grid;
    cfg.blockDim = block;
    cfg.dynamicSmemBytes = 0;
    cfg.stream = 0;
    cudaLaunchAttribute attr[1];
    attr[0].id = cudaLaunchAttributeProgrammaticStreamSerialization;
    attr[0].val.programmaticStreamSerializationAllowed = 1;
    cfg.attrs = attr;
    cfg.numAttrs = 1;
    cudaLaunchKernelEx(&cfg, kern, args...);
}

extern "C" void kernel_launch(void* const* d_in, const int* in_sizes, int n_in,
                              void* d_out, int out_size) {
    (void)in_sizes; (void)n_in; (void)out_size;
    const float* inputs   = (const float*)d_in[0];
    const float* pos_adj  = (const float*)d_in[1];
    const float* neg_adj  = (const float*)d_in[2];
    const float* Wih      = (const float*)d_in[3];
    const float* Whh      = (const float*)d_in[4];
    const float* bih      = (const float*)d_in[5];
    const float* bhh      = (const float*)d_in[6];
    const float* pos_W    = (const float*)d_in[7];
    const float* pos_Wu   = (const float*)d_in[8];
    const float* pos_Wv   = (const float*)d_in[9];
    const float* pos_b    = (const float*)d_in[10];
    const float* pos_projW= (const float*)d_in[11];
    const float* pos_projb= (const float*)d_in[12];
    const float* neg_W    = (const float*)d_in[13];
    const float* neg_Wu   = (const float*)d_in[14];
    const float* neg_Wv   = (const float*)d_in[15];
    const float* neg_b    = (const float*)d_in[16];
    const float* neg_projW= (const float*)d_in[17];
    const float* neg_projb= (const float*)d_in[18];
    const float* self_W   = (const float*)d_in[19];
    const float* self_b   = (const float*)d_in[20];
    const float* mlpp_W   = (const float*)d_in[21];
    const float* mlpp_b   = (const float*)d_in[22];
    const float* mlpn_W   = (const float*)d_in[23];
    const float* mlpn_b   = (const float*)d_in[24];
    const float* sem_W1   = (const float*)d_in[25];
    const float* sem_b1   = (const float*)d_in[26];
    const float* sem_W2   = (const float*)d_in[27];
    const float* pred_W   = (const float*)d_in[28];
    const float* pred_b   = (const float*)d_in[29];

    prep_kernel<<<48, 256>>>(Whh);
    launch_pdl(gru_kernel, dim3(NN / 4), dim3(64),
               inputs, Wih, bih, bhh,
               pos_W, neg_W, pos_Wu, pos_Wv, neg_Wu, neg_Wv);
    launch_pdl(attn_kernel, dim3(NN, 2), dim3(256), pos_adj, neg_adj);
    launch_pdl(comb_kernel, dim3(NN / 8), dim3(128),
               pos_b, pos_projW, pos_projb, neg_b, neg_projW, neg_projb,
               self_W, self_b, mlpp_W, mlpp_b, mlpn_W, mlpn_b,
               sem_W1, sem_b1, sem_W2);
    final_kernel<<<NN / 4, 128>>>(pred_W, pred_b, (float*)d_out);
}

// round 14
// speedup vs baseline: 1.0804x; 1.0008x over previous
#include <cuda_runtime.h>

#define NN 3000
#define TT 20
#define IND 6
#define HD 64
#define NH 8
#define MAXNZ 512

// ---------------- scratch (no allocation allowed) ----------------
__device__ ulonglong2 g_Whh4[(HD / 2) * 192];  // [kpair][row] -> (pk(w_k), pk(w_{k+1}))
__device__ float g_support[NN * HD];        // GRU final hidden
__device__ float g_s[2][NN * HD];           // per-graph head features  [n][h*8+f]
__device__ float g_f1[2][NH * NN];          // source scores  [g][h*N+n]
__device__ float g_f2[2][NH * NN];          // dest scores    [g][h*N+n]
__device__ unsigned g_f1maxI[16];           // encoded global per-(g,h) max of f1
__device__ float g_att[2][NN * HD];         // attention outputs
__device__ float g_emb[NN * HD];            // pre-pairnorm embedding
__device__ float g_colsum[HD];              // column sums for pairnorm mean

__device__ __forceinline__ float sigm(float x) { return 1.0f / (1.0f + __expf(-x)); }
__device__ __forceinline__ float tanhfast(float x) { return 2.0f * sigm(2.0f * x) - 1.0f; }

// order-preserving float<->uint encoding for atomicMax
__device__ __forceinline__ unsigned fenc(float f) {
    unsigned u = __float_as_uint(f);
    return (u & 0x80000000u) ? ~u : (u | 0x80000000u);
}
__device__ __forceinline__ float fdec(unsigned u) {
    return __uint_as_float((u & 0x80000000u) ? (u & 0x7fffffffu) : ~u);
}

// packed f32x2 helpers
__device__ __forceinline__ unsigned long long pk(float lo, float hi) {
    unsigned long long r;
    asm("mov.b64 %0, {%1,%2};" : "=l"(r) : "f"(lo), "f"(hi));
    return r;
}
__device__ __forceinline__ void upk(unsigned long long v, float& lo, float& hi) {
    asm("mov.b64 {%0,%1}, %2;" : "=f"(lo), "=f"(hi) : "l"(v));
}
__device__ __forceinline__ void ffma2(unsigned long long& d, unsigned long long a, unsigned long long b) {
    asm("fma.rn.f32x2 %0, %1, %2, %0;" : "+l"(d) : "l"(a), "l"(b));
}

// ---------------- K0: pack Whh into k-pair LDG.128 layout + init reductions ----------------
__global__ void prep_kernel(const float* __restrict__ Whh) {
    int i = blockIdx.x * 256 + threadIdx.x;
    if (i < 192 * HD) {
        int r = i >> 6, k = i & 63;
        float w = Whh[i];
        unsigned long long pw = pk(w, w);
        if (k & 1) g_Whh4[(k >> 1) * 192 + r].y = pw;
        else       g_Whh4[(k >> 1) * 192 + r].x = pw;
    }
    if (blockIdx.x == 0 && threadIdx.x < HD) g_colsum[threadIdx.x] = 0.f;
    if (blockIdx.x == 0 && threadIdx.x < 16) g_f1maxI[threadIdx.x] = 0u;
}

// ---------------- K1: GRU (4 nodes / 64-thread block), x-preload + ping-pong h,
//                  LDG.128 weight loads, fused head projection, PDL over prep ----------------
__global__ void __launch_bounds__(64) gru_kernel(
        const float* __restrict__ x, const float* __restrict__ Wih,
        const float* __restrict__ bih, const float* __restrict__ bhh,
        const float* __restrict__ Wp, const float* __restrict__ Wn,
        const float* __restrict__ Wup, const float* __restrict__ Wvp,
        const float* __restrict__ Wun, const float* __restrict__ Wvn) {
    __shared__ float4 shh4[2][HD];      // ping-pong: [buf][k] -> 4 nodes hidden
    __shared__ float shx[TT * IND * 4]; // [ (t*6+c)*4 + b ]
    int j = threadIdx.x;                // gate/hidden index 0..63
    int node0 = blockIdx.x * 4;         // 750 blocks

    // ---- prologue independent of prep: preload x, Wih, biases ----
#pragma unroll
    for (int e = j; e < TT * IND * 4; e += 64) {
        int b = e / (TT * IND), rem = e % (TT * IND);
        shx[rem * 4 + b] = x[node0 * (TT * IND) + e];
    }

    unsigned long long pwr[IND], pwz[IND], pwn[IND];
#pragma unroll
    for (int c = 0; c < IND; c++) {
        float a = Wih[j * IND + c];
        float b = Wih[(64 + j) * IND + c];
        float d = Wih[(128 + j) * IND + c];
        pwr[c] = pk(a, a); pwz[c] = pk(b, b); pwn[c] = pk(d, d);
    }
    float br  = bih[j] + bhh[j];
    float bz  = bih[64 + j] + bhh[64 + j];
    float bin = bih[128 + j];
    float bhn = bhh[128 + j];
    unsigned long long pbr = pk(br, br), pbz = pk(bz, bz);
    unsigned long long pbi = pk(bin, bin), pbh = pk(bhn, bhn);

    shh4[0][j] = make_float4(0.f, 0.f, 0.f, 0.f);
    float h0 = 0.f, h1 = 0.f, h2 = 0.f, h3 = 0.f;
    int cur = 0;

    cudaGridDependencySynchronize();    // g_Whh4 / g_colsum / g_f1maxI ready (prep done)
    __syncthreads();   // shx + zeroed shh visible

    for (int t = 0; t < TT; t++) {
        const float4* xt = (const float4*)(shx + t * IND * 4);

        unsigned long long ar01 = pbr, ar23 = pbr;
        unsigned long long az01 = pbz, az23 = pbz;
        unsigned long long an01 = pbi, an23 = pbi;
        unsigned long long gn01 = pbh, gn23 = pbh;

#pragma unroll
        for (int c = 0; c < IND; c++) {
            float4 xv = xt[c];
            unsigned long long x01 = pk(xv.x, xv.y), x23 = pk(xv.z, xv.w);
            ffma2(ar01, pwr[c], x01); ffma2(ar23, pwr[c], x23);
            ffma2(az01, pwz[c], x01); ffma2(az23, pwz[c], x23);
            ffma2(an01, pwn[c], x01); ffma2(an23, pwn[c], x23);
        }

        const float4* hbuf = shh4[cur];
#pragma unroll 4
        for (int p = 0; p < HD / 2; p++) {
            float4 hva = hbuf[2 * p], hvb = hbuf[2 * p + 1];
            unsigned long long ha01 = pk(hva.x, hva.y), ha23 = pk(hva.z, hva.w);
            unsigned long long hb01 = pk(hvb.x, hvb.y), hb23 = pk(hvb.z, hvb.w);
            ulonglong2 wr = g_Whh4[p * 192 + j];
            ulonglong2 wz = g_Whh4[p * 192 + 64 + j];
            ulonglong2 wn_ = g_Whh4[p * 192 + 128 + j];
            ffma2(ar01, wr.x, ha01);  ffma2(ar23, wr.x, ha23);
            ffma2(az01, wz.x, ha01);  ffma2(az23, wz.x, ha23);
            ffma2(gn01, wn_.x, ha01); ffma2(gn23, wn_.x, ha23);
            ffma2(ar01, wr.y, hb01);  ffma2(ar23, wr.y, hb23);
            ffma2(az01, wz.y, hb01);  ffma2(az23, wz.y, hb23);
            ffma2(gn01, wn_.y, hb01); ffma2(gn23, wn_.y, hb23);
        }

        float a0, a1, a2, a3, z0, z1, z2, z3, n0, n1, n2, n3, g0, g1, g2, g3;
        upk(ar01, a0, a1); upk(ar23, a2, a3);
        upk(az01, z0, z1); upk(az23, z2, z3);
        upk(an01, n0, n1); upk(an23, n2, n3);
        upk(gn01, g0, g1); upk(gn23, g2, g3);

        float r0 = sigm(a0), r1 = sigm(a1), r2 = sigm(a2), r3 = sigm(a3);
        float zz0 = sigm(z0), zz1 = sigm(z1), zz2 = sigm(z2), zz3 = sigm(z3);
        float nv0 = tanhfast(n0 + r0 * g0);
        float nv1 = tanhfast(n1 + r1 * g1);
        float nv2 = tanhfast(n2 + r2 * g2);
        float nv3 = tanhfast(n3 + r3 * g3);
        h0 = (1.f - zz0) * nv0 + zz0 * h0;
        h1 = (1.f - zz1) * nv1 + zz1 * h1;
        h2 = (1.f - zz2) * nv2 + zz2 * h2;
        h3 = (1.f - zz3) * nv3 + zz3 * h3;
        shh4[cur ^ 1][j] = make_float4(h0, h1, h2, h3);
        __syncthreads();   // single barrier: write visibility + read anti-dep
        cur ^= 1;
    }

    g_support[(node0 + 0) * HD + j] = h0;
    g_support[(node0 + 1) * HD + j] = h1;
    g_support[(node0 + 2) * HD + j] = h2;
    g_support[(node0 + 3) * HD + j] = h3;

    // ------ fused head projection: s = h @ W, f1/f2, global f1 max ------
    int hh = j >> 3, f = j & 7;
    const float* hsm = (const float*)shh4[cur];   // [k*4 + b]
#pragma unroll
    for (int g = 0; g < 2; g++) {
        const float* W  = g ? Wn  : Wp;
        float wu = (g ? Wun : Wup)[hh * 8 + f];
        float wv = (g ? Wvn : Wvp)[hh * 8 + f];
        float acc[4] = {0.f, 0.f, 0.f, 0.f};
#pragma unroll 4
        for (int k = 0; k < HD; k++) {
            float w = W[k * HD + j];
#pragma unroll
            for (int b = 0; b < 4; b++) acc[b] += hsm[k * 4 + b] * w;
        }
#pragma unroll
        for (int b = 0; b < 4; b++) {
            int n = node0 + b;
            g_s[g][n * HD + j] = acc[b];
            float t1 = acc[b] * wu, t2 = acc[b] * wv;
#pragma unroll
            for (int o = 4; o; o >>= 1) {
                t1 += __shfl_xor_sync(0xffffffffu, t1, o);
                t2 += __shfl_xor_sync(0xffffffffu, t2, o);
            }
            if (f == 0) {
                g_f1[g][hh * NN + n] = t1;
                g_f2[g][hh * NN + n] = t2;
                atomicMax(&g_f1maxI[g * 8 + hh], fenc(t1));
            }
        }
    }
}

// ---------------- K3: sparse masked attention; compaction overlapped with GRU via PDL;
//                  transposed gather (4 neighbors/warp-iter, 8 lanes/neighbor) ----------------
__global__ void attn_kernel(const float* __restrict__ adj0, const float* __restrict__ adj1) {
    int i = blockIdx.x, g = blockIdx.y;
    const float* row = (g ? adj1 : adj0) + (size_t)i * NN;
    __shared__ short idx[MAXNZ];
    __shared__ int cnts[8];
    int tid = threadIdx.x, warp = tid >> 5, lane = tid & 31;

    // ===== pre-sync phase: depends only on the adjacency input =====
    const float4* row4 = (const float4*)row;   // N=3000 divisible by 4
    float4 v[3];
#pragma unroll
    for (int it = 0; it < 3; it++) {
        int q = it * 256 + tid;
        v[it] = (q < NN / 4) ? row4[q] : make_float4(0.f, 0.f, 0.f, 0.f);
    }

    // phase A: record ballot masks + per-warp count (no atomics)
    unsigned bal[12];
    int wcnt = 0;
#pragma unroll
    for (int it = 0; it < 3; it++) {
#pragma unroll
        for (int c = 0; c < 4; c++) {
            float val = (c == 0) ? v[it].x : (c == 1) ? v[it].y : (c == 2) ? v[it].z : v[it].w;
            unsigned b = __ballot_sync(0xffffffffu, val != 0.f);
            bal[it * 4 + c] = b;
            wcnt += __popc(b);
        }
    }
    if (lane == 0) cnts[warp] = wcnt;
    __syncthreads();

    int base = 0, m = 0;
#pragma unroll
    for (int s = 0; s < 8; s++) {
        int cs = cnts[s];
        if (s < warp) base += cs;
        m += cs;
    }
    m = min(m, MAXNZ);

    // phase B: replay stored masks into exact slots
    unsigned ltmask = (1u << lane) - 1u;
    int off = base;
#pragma unroll
    for (int it = 0; it < 3; it++) {
        int q = it * 256 + tid;
#pragma unroll
        for (int c = 0; c < 4; c++) {
            unsigned b = bal[it * 4 + c];
            if (b) {
                float val = (c == 0) ? v[it].x : (c == 1) ? v[it].y : (c == 2) ? v[it].z : v[it].w;
                if (val != 0.f) {
                    int p = off + __popc(b & ltmask);
                    if (p < MAXNZ) idx[p] = (short)(4 * q + c);
                }
                off += __popc(b);
            }
        }
    }
    __syncthreads();

    // ===== wait for GRU outputs (f1/f2/s/f1max), then gather =====
    cudaGridDependencySynchronize();

    int h = warp;                             // warp = head
    int grp = lane >> 3, f = lane & 7;        // 4 neighbor-groups x 8 features
    const float* f1h = g_f1[g] + h * NN;
    float f2v = g_f2[g][h * NN + i];
    // shift M >= max over row nonzeros (leaky monotone; softmax shift-invariant)
    float Mv = fdec(g_f1maxI[g * 8 + h]) + f2v;
    Mv = Mv >= 0.f ? Mv : 0.2f * Mv;
    const float* sb = g_s[g];

    float accf = 0.f;   // feature-f partial over this group's neighbor stripe
    float se = 0.f;     // exp-sum: contributed only by f==0 lanes
    for (int k = grp; k < m; k += 4) {
        int jj = idx[k];                          // LDS: 4 distinct values/warp
        float vv = f1h[jj] + f2v;                 // 4 sectors/warp (8-lane broadcast)
        vv = vv >= 0.f ? vv : 0.2f * vv;
        float e = __expf(vv - Mv);
        float sv = sb[jj * HD + h * 8 + f];       // 4 x 32B sectors/warp
        accf += e * sv;
        se += (f == 0) ? e : 0.f;
    }
    // reduce across the 4 groups (feature lanes align mod 8)
    accf += __shfl_xor_sync(0xffffffffu, accf, 8);
    accf += __shfl_xor_sync(0xffffffffu, accf, 16);
    se += __shfl_xor_sync(0xffffffffu, se, 8);
    se += __shfl_xor_sync(0xffffffffu, se, 16);
    se = __shfl_sync(0xffffffffu, se, 0);
    if (lane < 8) {
        float inv = se > 0.f ? 1.0f / se : 0.f;   // empty row -> zeros (matches ref mask)
        g_att[g][i * HD + h * 8 + lane] = accf * inv;
    }
}

// ---------------- K4: warp-per-2-nodes, float2 channel pairing; PDL over attn ----------------
__global__ void __launch_bounds__(128) comb_kernel(
        const float* __restrict__ pos_b, const float* __restrict__ pWp, const float* __restrict__ pbp,
        const float* __restrict__ neg_b, const float* __restrict__ pWn, const float* __restrict__ pbn,
        const float* __restrict__ selfW, const float* __restrict__ selfb,
        const float* __restrict__ mpW, const float* __restrict__ mpb,
        const float* __restrict__ mnW, const float* __restrict__ mnb,
        const float* __restrict__ semW1, const float* __restrict__ semb1,
        const float* __restrict__ semW2) {
    __shared__ float sb[4][12][HD];     // per-warp staging
    __shared__ float colacc[HD];
    int tid = threadIdx.x, warp = tid >> 5, lane = tid & 31;
    int nA = blockIdx.x * 8 + warp * 2;   // 375*8 = 3000 exact
    int nB = nA + 1;
    int c0 = 2 * lane, c1 = 2 * lane + 1;

    if (tid < HD) colacc[tid] = 0.f;

    const float2* pWp2 = (const float2*)pWp;
    const float2* pWn2 = (const float2*)pWn;
    const float2* sfW2 = (const float2*)selfW;
    const float2* mpW2 = (const float2*)mpW;
    const float2* mnW2 = (const float2*)mnW;
    const float2* sm12 = (const float2*)semW1;

    float (*S)[HD] = sb[warp];
    // prologue: support + biases (gru outputs — already complete before attn ran)
    {
        float2 sA = ((const float2*)(g_support + nA * HD))[lane];
        float2 sB = ((const float2*)(g_support + nB * HD))[lane];
        S[0][c0] = sA.x; S[0][c1] = sA.y;
        S[1][c0] = sB.x; S[1][c1] = sB.y;
    }
    float2 pb2  = ((const float2*)pos_b)[lane];
    float2 pbp2 = ((const float2*)pbp)[lane];
    float2 nb2  = ((const float2*)neg_b)[lane];
    float2 pbn2 = ((const float2*)pbn)[lane];
    float2 sfb2 = ((const float2*)selfb)[lane];
    __syncthreads();

    // wait for attn outputs before reading g_att
    cudaGridDependencySynchronize();

    float2 atpA = ((const float2*)(g_att[0] + nA * HD))[lane];
    float2 atpB = ((const float2*)(g_att[0] + nB * HD))[lane];
    float2 atnA = ((const float2*)(g_att[1] + nA * HD))[lane];
    float2 atnB = ((const float2*)(g_att[1] + nB * HD))[lane];
    float apA0 = atpA.x + pb2.x + pbp2.x, apA1 = atpA.y + pb2.y + pbp2.y;
    float apB0 = atpB.x + pb2.x + pbp2.x, apB1 = atpB.y + pb2.y + pbp2.y;
    float anA0 = atnA.x + nb2.x + pbn2.x, anA1 = atnA.y + nb2.y + pbn2.y;
    float anB0 = atnB.x + nb2.x + pbn2.x, anB1 = atnB.y + nb2.y + pbn2.y;
    float svA0 = sfb2.x, svA1 = sfb2.y, svB0 = sfb2.x, svB1 = sfb2.y;
#pragma unroll 8
    for (int k = 0; k < HD; k++) {
        float sA = S[0][k], sBv = S[1][k];
        float2 wp = pWp2[k * 32 + lane];
        float2 wn = pWn2[k * 32 + lane];
        float2 ws = sfW2[k * 32 + lane];
        apA0 += sA * wp.x;  apA1 += sA * wp.y;  apB0 += sBv * wp.x;  apB1 += sBv * wp.y;
        anA0 += sA * wn.x;  anA1 += sA * wn.y;  anB0 += sBv * wn.x;  anB1 += sBv * wn.y;
        svA0 += sA * ws.x;  svA1 += sA * ws.y;  svB0 += sBv * ws.x;  svB1 += sBv * ws.y;
    }
    S[2][c0] = apA0; S[2][c1] = apA1; S[3][c0] = apB0; S[3][c1] = apB1;
    S[4][c0] = anA0; S[4][c1] = anA1; S[5][c0] = anB0; S[5][c1] = anB1;
    __syncwarp();

    // ---- phase 2 ----
    float2 mpb2 = ((const float2*)mpb)[lane];
    float2 mnb2 = ((const float2*)mnb)[lane];
    float spA0 = mpb2.x, spA1 = mpb2.y, spB0 = mpb2.x, spB1 = mpb2.y;
    float snA0 = mnb2.x, snA1 = mnb2.y, snB0 = mnb2.x, snB1 = mnb2.y;
#pragma unroll 8
    for (int k = 0; k < HD; k++) {
        float pA = S[2][k], pB = S[3][k], qA = S[4][k], qB = S[5][k];
        float2 w = mpW2[k * 32 + lane];
        float2 v = mnW2[k * 32 + lane];
        spA0 += pA * w.x; spA1 += pA * w.y; spB0 += pB * w.x; spB1 += pB * w.y;
        snA0 += qA * v.x; snA1 += qA * v.y; snB0 += qB * v.x; snB1 += qB * v.y;
    }
    S[6][c0] = svA0; S[6][c1] = svA1; S[7][c0] = svB0; S[7][c1] = svB1;
    S[8][c0] = spA0; S[8][c1] = spA1; S[9][c0] = spB0; S[9][c1] = spB1;
    S[10][c0] = snA0; S[10][c1] = snA1; S[11][c0] = snB0; S[11][c1] = snB1;
    __syncwarp();

    // ---- phase 3: semantic attention logits ----
    float2 sb12 = ((const float2*)semb1)[lane];
    float tA00 = sb12.x, tA01 = sb12.y, tA10 = sb12.x, tA11 = sb12.y, tA20 = sb12.x, tA21 = sb12.y;
    float tB00 = sb12.x, tB01 = sb12.y, tB10 = sb12.x, tB11 = sb12.y, tB20 = sb12.x, tB21 = sb12.y;
#pragma unroll 8
    for (int k = 0; k < HD; k++) {
        float2 w = sm12[k * 32 + lane];
        float e0A = S[6][k], e0B = S[7][k];
        float e1A = S[8][k], e1B = S[9][k];
        float e2A = S[10][k], e2B = S[11][k];
        tA00 += e0A * w.x; tA01 += e0A * w.y; tB00 += e0B * w.x; tB01 += e0B * w.y;
        tA10 += e1A * w.x; tA11 += e1A * w.y; tB10 += e1B * w.x; tB11 += e1B * w.y;
        tA20 += e2A * w.x; tA21 += e2A * w.y; tB20 += e2B * w.x; tB21 += e2B * w.y;
    }
    float2 w22 = ((const float2*)semW2)[lane];
    float uA0 = tanhfast(tA00) * w22.x + tanhfast(tA01) * w22.y;
    float uA1 = tanhfast(tA10) * w22.x + tanhfast(tA11) * w22.y;
    float uA2 = tanhfast(tA20) * w22.x + tanhfast(tA21) * w22.y;
    float uB0 = tanhfast(tB00) * w22.x + tanhfast(tB01) * w22.y;
    float uB1 = tanhfast(tB10) * w22.x + tanhfast(tB11) * w22.y;
    float uB2 = tanhfast(tB20) * w22.x + tanhfast(tB21) * w22.y;
#pragma unroll
    for (int o = 16; o; o >>= 1) {
        uA0 += __shfl_xor_sync(0xffffffffu, uA0, o);
        uA1 += __shfl_xor_sync(0xffffffffu, uA1, o);
        uA2 += __shfl_xor_sync(0xffffffffu, uA2, o);
        uB0 += __shfl_xor_sync(0xffffffffu, uB0, o);
        uB1 += __shfl_xor_sync(0xffffffffu, uB1, o);
        uB2 += __shfl_xor_sync(0xffffffffu, uB2, o);
    }
    float mA = fmaxf(uA0, fmaxf(uA1, uA2));
    float eA0 = __expf(uA0 - mA), eA1 = __expf(uA1 - mA), eA2 = __expf(uA2 - mA);
    float invA = 1.f / (eA0 + eA1 + eA2);
    float embA0 = (eA0 * svA0 + eA1 * spA0 + eA2 * snA0) * invA;
    float embA1 = (eA0 * svA1 + eA1 * spA1 + eA2 * snA1) * invA;
    float mB = fmaxf(uB0, fmaxf(uB1, uB2));
    float eB0 = __expf(uB0 - mB), eB1 = __expf(uB1 - mB), eB2 = __expf(uB2 - mB);
    float invB = 1.f / (eB0 + eB1 + eB2);
    float embB0 = (eB0 * svB0 + eB1 * spB0 + eB2 * snB0) * invB;
    float embB1 = (eB0 * svB1 + eB1 * spB1 + eB2 * snB1) * invB;

    ((float2*)(g_emb + nA * HD))[lane] = make_float2(embA0, embA1);
    ((float2*)(g_emb + nB * HD))[lane] = make_float2(embB0, embB1);
    atomicAdd(&colacc[c0], embA0 + embB0);
    atomicAdd(&colacc[c1], embA1 + embB1);
    __syncthreads();
    if (tid < HD) atomicAdd(&g_colsum[tid], colacc[tid]);
}

// ---------------- K5: pairnorm + prediction head (warp per node) ----------------
__global__ void final_kernel(const float* __restrict__ predW, const float* __restrict__ predb,
                             float* __restrict__ out) {
    int warp = threadIdx.x >> 5, lane = threadIdx.x & 31;
    int n = blockIdx.x * 4 + warp;
    float invn = 1.0f / NN;
    float x0 = g_emb[n * HD + lane]      - g_colsum[lane]      * invn;
    float x1 = g_emb[n * HD + 32 + lane] - g_colsum[32 + lane] * invn;
    float ss = x0 * x0 + x1 * x1;
    float dt = x0 * predW[lane] + x1 * predW[32 + lane];
#pragma unroll
    for (int o = 16; o; o >>= 1) {
        ss += __shfl_xor_sync(0xffffffffu, ss, o);
        dt += __shfl_xor_sync(0xffffffffu, dt, o);
    }
    if (lane == 0) out[n] = sigm(dt * rsqrtf(1e-6f + ss) + predb[0]);
}

// ---------------- launch (PDL on gru/attn/comb) ----------------
template <typename... Args>
static void launch_pdl(void (*kern)(Args...), dim3 grid, dim3 block, Args... args) {
    cudaLaunchConfig_t cfg = {};
    cfg.gridDim = grid;
    cfg.blockDim = block;
    cfg.dynamicSmemBytes = 0;
    cfg.stream = 0;
    cudaLaunchAttribute attr[1];
    attr[0].id = cudaLaunchAttributeProgrammaticStreamSerialization;
    attr[0].val.programmaticStreamSerializationAllowed = 1;
    cfg.attrs = attr;
    cfg.numAttrs = 1;
    cudaLaunchKernelEx(&cfg, kern, args...);
}

extern "C" void kernel_launch(void* const* d_in, const int* in_sizes, int n_in,
                              void* d_out, int out_size) {
    (void)in_sizes; (void)n_in; (void)out_size;
    const float* inputs   = (const float*)d_in[0];
    const float* pos_adj  = (const float*)d_in[1];
    const float* neg_adj  = (const float*)d_in[2];
    const float* Wih      = (const float*)d_in[3];
    const float* Whh      = (const float*)d_in[4];
    const float* bih      = (const float*)d_in[5];
    const float* bhh      = (const float*)d_in[6];
    const float* pos_W    = (const float*)d_in[7];
    const float* pos_Wu   = (const float*)d_in[8];
    const float* pos_Wv   = (const float*)d_in[9];
    const float* pos_b    = (const float*)d_in[10];
    const float* pos_projW= (const float*)d_in[11];
    const float* pos_projb= (const float*)d_in[12];
    const float* neg_W    = (const float*)d_in[13];
    const float* neg_Wu   = (const float*)d_in[14];
    const float* neg_Wv   = (const float*)d_in[15];
    const float* neg_b    = (const float*)d_in[16];
    const float* neg_projW= (const float*)d_in[17];
    const float* neg_projb= (const float*)d_in[18];
    const float* self_W   = (const float*)d_in[19];
    const float* self_b   = (const float*)d_in[20];
    const float* mlpp_W   = (const float*)d_in[21];
    const float* mlpp_b   = (const float*)d_in[22];
    const float* mlpn_W   = (const float*)d_in[23];
    const float* mlpn_b   = (const float*)d_in[24];
    const float* sem_W1   = (const float*)d_in[25];
    const float* sem_b1   = (const float*)d_in[26];
    const float* sem_W2   = (const float*)d_in[27];
    const float* pred_W   = (const float*)d_in[28];
    const float* pred_b   = (const float*)d_in[29];

    prep_kernel<<<48, 256>>>(Whh);
    launch_pdl(gru_kernel, dim3(NN / 4), dim3(64),
               inputs, Wih, bih, bhh,
               pos_W, neg_W, pos_Wu, pos_Wv, neg_Wu, neg_Wv);
    launch_pdl(attn_kernel, dim3(NN, 2), dim3(256), pos_adj, neg_adj);
    launch_pdl(comb_kernel, dim3(NN / 8), dim3(128),
               pos_b, pos_projW, pos_projb, neg_b, neg_projW, neg_projb,
               self_W, self_b, mlpp_W, mlpp_b, mlpn_W, mlpn_b,
               sem_W1, sem_b1, sem_W2);
    final_kernel<<<NN / 4, 128>>>(pred_W, pred_b, (float*)d_out);
}